// round 1
// baseline (speedup 1.0000x reference)
#include <cuda_runtime.h>
#include <cstdint>

// Problem constants
#define B_    8
#define CIN   64
#define COUT  64
#define L_    16384
#define KK    5
#define PAD_  2
#define LP    (L_ + 2*PAD_)      // 16388

// Tiling
#define TP    128   // positions per block
#define CH    32    // channel chunk for GEMM K-dim
#define VSTR  132   // vs row stride (pad for bank conflicts, 16B aligned)

// Scratch: channel-last x (unpadded; reflect handled via index mapping)
__device__ float g_xt[B_ * L_ * CIN];          // [b][l][c]  ~33.5 MB
__device__ float g_wt[KK * CIN * COUT];        // [(k*64+c)][o]

// ---------------------------------------------------------------------------
// x (B,C,L) -> xt (B,L,C), 32x32 smem tile transpose
// ---------------------------------------------------------------------------
__global__ void transpose_x_kernel(const float* __restrict__ x) {
    __shared__ float tile[32][33];
    int b  = blockIdx.z;
    int l0 = blockIdx.x * 32;
    int c0 = blockIdx.y * 32;
    int tx = threadIdx.x;      // 32
    int ty = threadIdx.y;      // 8
    const float* xb = x + (size_t)b * CIN * L_;
    #pragma unroll
    for (int i = 0; i < 4; i++) {
        int c = c0 + ty + i * 8;
        tile[ty + i * 8][tx] = xb[(size_t)c * L_ + l0 + tx];
    }
    __syncthreads();
    float* xtb = g_xt + (size_t)b * L_ * CIN;
    #pragma unroll
    for (int i = 0; i < 4; i++) {
        int l = l0 + ty + i * 8;
        xtb[(size_t)l * CIN + c0 + tx] = tile[tx][ty + i * 8];
    }
}

// ---------------------------------------------------------------------------
// weight (o, c, k) -> wt[(k*64+c)][o]
// ---------------------------------------------------------------------------
__global__ void transpose_w_kernel(const float* __restrict__ w) {
    int q = blockIdx.x;          // 0..319 : q = k*64 + c
    int o = threadIdx.x;         // 0..63
    int k = q >> 6;
    int c = q & 63;
    g_wt[q * COUT + o] = w[o * (CIN * KK) + c * KK + k];
}

// ---------------------------------------------------------------------------
// Main kernel: tile = 128 positions x 64 outputs, K-dim = 320 in 10 chunks of 32
// ---------------------------------------------------------------------------
__global__ __launch_bounds__(256) void deform_main_kernel(
    const float* __restrict__ off,    // (B,1,L,K)
    const float* __restrict__ bias,   // (COUT)
    float* __restrict__ out)          // (B,COUT,L)
{
    __shared__ float fr[KK][TP];
    __shared__ int   j0s[KK][TP];
    __shared__ int   j1s[KK][TP];
    __shared__ float vs[CH][VSTR];    // interp values, [c][p]
    __shared__ float ws[CH][COUT];    // weight chunk,  [c][o]
    __shared__ float bsh[COUT];

    const int b   = blockIdx.y;
    const int lo0 = blockIdx.x * TP;
    const int t   = threadIdx.x;

    if (t < COUT) bsh[t] = bias[t];

    // ---- interp parameters: 128 pos x 5 taps ----
    const float* offb = off + ((size_t)b * L_ + lo0) * KK;
    for (int idx = t; idx < TP * KK; idx += 256) {
        int p = idx / KK;
        int k = idx % KK;
        float o_ = offb[idx];
        float T = (float)(lo0 + p + k) + o_;
        T = fminf(fmaxf(T, 0.0f), (float)(LP - 1));
        int i0 = (int)floorf(T);
        i0 = min(max(i0, 0), LP - 2);
        float f = T - (float)i0;
        int j0 = i0 - PAD_;
        int j1 = i0 + 1 - PAD_;
        j0 = (j0 < 0) ? -j0 : j0;
        j1 = (j1 < 0) ? -j1 : j1;
        if (j0 >= L_) j0 = 2 * L_ - 2 - j0;
        if (j1 >= L_) j1 = 2 * L_ - 2 - j1;
        fr[k][p]  = f;
        j0s[k][p] = j0;
        j1s[k][p] = j1;
    }
    __syncthreads();

    // micro-tile mapping: 8 pos x 4 out per thread
    const int tx = t & 15;          // -> output
    const int ty = t >> 4;          // -> position group
    const int o0 = tx * 4;
    const int p0 = ty * 8;

    float acc[8][4];
    #pragma unroll
    for (int i = 0; i < 8; i++)
        #pragma unroll
        for (int j = 0; j < 4; j++) acc[i][j] = 0.0f;

    const float* xtb = g_xt + (size_t)b * L_ * CIN;
    const int cc = t & 31;          // channel within chunk (build phase)
    const int pb = t >> 5;          // position base (build phase)

    for (int ch = 0; ch < 10; ch++) {
        const int k  = ch >> 1;
        const int c0 = (ch & 1) * CH;

        // weight chunk -> smem (contiguous 2048 floats)
        {
            const float4* wsrc = (const float4*)(g_wt + (k * CIN + c0) * COUT);
            float4* wdst = (float4*)&ws[0][0];
            wdst[t]       = wsrc[t];
            wdst[t + 256] = wsrc[t + 256];
        }

        // build interp chunk vs[c][p]
        #pragma unroll
        for (int pi = 0; pi < 16; pi++) {
            int p = pb + pi * 8;
            float f = fr[k][p];
            const float* r0 = xtb + (size_t)j0s[k][p] * CIN + c0 + cc;
            const float* r1 = xtb + (size_t)j1s[k][p] * CIN + c0 + cc;
            float g0 = __ldg(r0);
            float g1 = __ldg(r1);
            vs[cc][p] = g0 + f * (g1 - g0);
        }
        __syncthreads();

        // GEMM over this chunk
        #pragma unroll
        for (int kki = 0; kki < CH; kki++) {
            float4 bv = *(const float4*)&ws[kki][o0];
            float4 a0 = *(const float4*)&vs[kki][p0];
            float4 a1 = *(const float4*)&vs[kki][p0 + 4];
            float av[8] = {a0.x, a0.y, a0.z, a0.w, a1.x, a1.y, a1.z, a1.w};
            float bb[4] = {bv.x, bv.y, bv.z, bv.w};
            #pragma unroll
            for (int i = 0; i < 8; i++)
                #pragma unroll
                for (int j = 0; j < 4; j++)
                    acc[i][j] += av[i] * bb[j];
        }
        __syncthreads();
    }

    // ---- epilogue: stage through smem for coalesced stores ----
    const int pw = t & 127;      // position for store
    const int ob = t >> 7;       // 0..1
    #pragma unroll
    for (int pass = 0; pass < 2; pass++) {
        if (pass) __syncthreads();
        if ((tx >> 3) == pass) {
            #pragma unroll
            for (int j = 0; j < 4; j++)
                #pragma unroll
                for (int i = 0; i < 8; i++)
                    vs[(o0 & 31) + j][p0 + i] = acc[i][j];
        }
        __syncthreads();
        #pragma unroll
        for (int oi = 0; oi < 16; oi++) {
            int oo = ob + oi * 2;
            int o  = pass * 32 + oo;
            out[((size_t)b * COUT + o) * L_ + lo0 + pw] = vs[oo][pw] + bsh[o];
        }
    }
}

// ---------------------------------------------------------------------------
extern "C" void kernel_launch(void* const* d_in, const int* in_sizes, int n_in,
                              void* d_out, int out_size) {
    const float* x      = (const float*)d_in[0];
    const float* off    = (const float*)d_in[1];
    const float* weight = (const float*)d_in[2];
    const float* bias   = (const float*)d_in[3];
    float* out          = (float*)d_out;

    dim3 tg(L_ / 32, CIN / 32, B_);
    transpose_x_kernel<<<tg, dim3(32, 8)>>>(x);
    transpose_w_kernel<<<KK * CIN, COUT>>>(weight);

    dim3 mg(L_ / TP, B_);
    deform_main_kernel<<<mg, 256>>>(off, bias, out);
}

// round 2
// speedup vs baseline: 1.4641x; 1.4641x over previous
#include <cuda_runtime.h>
#include <cuda_bf16.h>
#include <cstdint>

// Problem constants
#define B_    8
#define CIN   64
#define COUT  64
#define L_    16384
#define KK    5
#define PAD_  2
#define LP    (L_ + 2*PAD_)      // 16388

// Tiling
#define TP    128   // positions per block (M tile)
#define KC    32    // K chunk (channels per chunk; tap handled per 2 chunks)
#define AK    40    // smem row stride in bf16 elems (80 B, conflict-free for ldmatrix)

// Scratch
__device__ float g_xt[B_ * L_ * CIN];                 // channel-last x  [b][l][c]
__device__ __nv_bfloat16 g_wh[COUT * KK * CIN];       // weight hi  [o][k*64+c]
__device__ __nv_bfloat16 g_wl[COUT * KK * CIN];       // weight lo

// ---------------------------------------------------------------------------
// x (B,C,L) -> xt (B,L,C)
// ---------------------------------------------------------------------------
__global__ void transpose_x_kernel(const float* __restrict__ x) {
    __shared__ float tile[32][33];
    int b  = blockIdx.z;
    int l0 = blockIdx.x * 32;
    int c0 = blockIdx.y * 32;
    int tx = threadIdx.x, ty = threadIdx.y;
    const float* xb = x + (size_t)b * CIN * L_;
    #pragma unroll
    for (int i = 0; i < 4; i++)
        tile[ty + i * 8][tx] = xb[(size_t)(c0 + ty + i * 8) * L_ + l0 + tx];
    __syncthreads();
    float* xtb = g_xt + (size_t)b * L_ * CIN;
    #pragma unroll
    for (int i = 0; i < 4; i++)
        xtb[(size_t)(l0 + ty + i * 8) * CIN + c0 + tx] = tile[tx][ty + i * 8];
}

// ---------------------------------------------------------------------------
// weight (o,c,k) -> split bf16 hi/lo at [o][k*64+c]
// ---------------------------------------------------------------------------
__global__ void wsplit_kernel(const float* __restrict__ w) {
    int q = blockIdx.x;          // q = k*64 + c
    int o = threadIdx.x;
    int k = q >> 6;
    int c = q & 63;
    float v = w[o * (CIN * KK) + c * KK + k];
    __nv_bfloat16 hi = __float2bfloat16(v);
    __nv_bfloat16 lo = __float2bfloat16(v - __bfloat162float(hi));
    g_wh[o * (KK * CIN) + q] = hi;
    g_wl[o * (KK * CIN) + q] = lo;
}

// ---------------------------------------------------------------------------
// MMA helpers
// ---------------------------------------------------------------------------
__device__ __forceinline__ void ldm_x4(uint32_t& r0, uint32_t& r1, uint32_t& r2, uint32_t& r3,
                                       const void* p) {
    uint32_t a = (uint32_t)__cvta_generic_to_shared(p);
    asm volatile("ldmatrix.sync.aligned.m8n8.x4.shared.b16 {%0,%1,%2,%3}, [%4];"
                 : "=r"(r0), "=r"(r1), "=r"(r2), "=r"(r3) : "r"(a));
}

__device__ __forceinline__ void mma_bf16(float* c, const uint32_t* a, const uint32_t* b) {
    asm volatile(
        "mma.sync.aligned.m16n8k16.row.col.f32.bf16.bf16.f32 "
        "{%0,%1,%2,%3}, {%4,%5,%6,%7}, {%8,%9}, {%0,%1,%2,%3};"
        : "+f"(c[0]), "+f"(c[1]), "+f"(c[2]), "+f"(c[3])
        : "r"(a[0]), "r"(a[1]), "r"(a[2]), "r"(a[3]), "r"(b[0]), "r"(b[1]));
}

// ---------------------------------------------------------------------------
// Main kernel: tile = 128 positions x 64 outputs
// ---------------------------------------------------------------------------
struct SMemMain {
    float fr[KK][TP];
    int   j0[KK][TP];
    int   j1[KK][TP];
    __nv_bfloat16 Ah[TP][AK];
    __nv_bfloat16 Al[TP][AK];
    __nv_bfloat16 Wh[COUT][AK];
    __nv_bfloat16 Wl[COUT][AK];
};
union SMemU {
    SMemMain m;
    float stage[COUT][TP + 4];
};

__global__ __launch_bounds__(256, 2) void deform_main_kernel(
    const float* __restrict__ off,
    const float* __restrict__ bias,
    float* __restrict__ out)
{
    __shared__ SMemU sm;
    __shared__ float bsh[COUT];

    const int b   = blockIdx.y;
    const int lo0 = blockIdx.x * TP;
    const int t   = threadIdx.x;
    const int lane = t & 31;
    const int wid  = t >> 5;

    if (t < COUT) bsh[t] = bias[t];

    // ---- interp params ----
    const float* offb = off + ((size_t)b * L_ + lo0) * KK;
    for (int idx = t; idx < TP * KK; idx += 256) {
        int p = idx / KK;
        int k = idx % KK;
        float T = (float)(lo0 + p + k) + offb[idx];
        T = fminf(fmaxf(T, 0.0f), (float)(LP - 1));
        int i0 = (int)floorf(T);
        i0 = min(max(i0, 0), LP - 2);
        float f = T - (float)i0;
        int j0 = i0 - PAD_;
        int j1 = i0 + 1 - PAD_;
        j0 = (j0 < 0) ? -j0 : j0;
        j1 = (j1 < 0) ? -j1 : j1;
        if (j0 >= L_) j0 = 2 * L_ - 2 - j0;
        if (j1 >= L_) j1 = 2 * L_ - 2 - j1;
        sm.m.fr[k][p] = f;
        sm.m.j0[k][p] = j0;
        sm.m.j1[k][p] = j1;
    }
    __syncthreads();

    // warp tiling: 4 (M) x 2 (N); warp tile 32x32
    const int m0 = (wid & 3) * 32;
    const int n0 = (wid >> 2) * 32;

    float acc[2][4][4];
    #pragma unroll
    for (int i = 0; i < 2; i++)
        #pragma unroll
        for (int j = 0; j < 4; j++)
            #pragma unroll
            for (int r = 0; r < 4; r++) acc[i][j][r] = 0.0f;

    const float* xtb = g_xt + (size_t)b * L_ * CIN;
    const int cp = t & 15;    // channel-pair
    const int pb = t >> 4;    // pos base (0..15)

    for (int ch = 0; ch < 10; ch++) {
        const int k  = ch >> 1;
        const int c0 = (ch & 1) * KC;

        // weight chunk -> smem (hi & lo)
        {
            int o    = t >> 2;
            int quad = t & 3;
            *(uint4*)&sm.m.Wh[o][quad * 8] =
                *(const uint4*)&g_wh[o * (KK * CIN) + ch * KC + quad * 8];
            *(uint4*)&sm.m.Wl[o][quad * 8] =
                *(const uint4*)&g_wl[o * (KK * CIN) + ch * KC + quad * 8];
        }

        // build interp chunk (split bf16)
        #pragma unroll
        for (int pi = 0; pi < 8; pi++) {
            int p = pb + pi * 16;
            float f  = sm.m.fr[k][p];
            int j0   = sm.m.j0[k][p];
            int j1   = sm.m.j1[k][p];
            float2 g0 = *(const float2*)(xtb + (size_t)j0 * CIN + c0 + cp * 2);
            float2 g1 = *(const float2*)(xtb + (size_t)j1 * CIN + c0 + cp * 2);
            float v0 = fmaf(f, g1.x - g0.x, g0.x);
            float v1 = fmaf(f, g1.y - g0.y, g0.y);
            __nv_bfloat162 hi;
            hi.x = __float2bfloat16(v0);
            hi.y = __float2bfloat16(v1);
            __nv_bfloat162 lo;
            lo.x = __float2bfloat16(v0 - __bfloat162float(hi.x));
            lo.y = __float2bfloat16(v1 - __bfloat162float(hi.y));
            *(__nv_bfloat162*)&sm.m.Ah[p][cp * 2] = hi;
            *(__nv_bfloat162*)&sm.m.Al[p][cp * 2] = lo;
        }
        __syncthreads();

        // ---- MMA over this chunk: K=32 = 2 x k16 ----
        #pragma unroll
        for (int ks = 0; ks < 2; ks++) {
            uint32_t ah[2][4], al[2][4], bh[4][2], bl[4][2];
            int arow = (lane & 15);
            int acol = ks * 16 + (lane >> 4) * 8;
            #pragma unroll
            for (int mi = 0; mi < 2; mi++) {
                ldm_x4(ah[mi][0], ah[mi][1], ah[mi][2], ah[mi][3],
                       &sm.m.Ah[m0 + mi * 16 + arow][acol]);
                ldm_x4(al[mi][0], al[mi][1], al[mi][2], al[mi][3],
                       &sm.m.Al[m0 + mi * 16 + arow][acol]);
            }
            int bn = (lane >> 2);
            int bk = ks * 16 + (lane & 3) * 2;
            #pragma unroll
            for (int ni = 0; ni < 4; ni++) {
                bh[ni][0] = *(const uint32_t*)&sm.m.Wh[n0 + ni * 8 + bn][bk];
                bh[ni][1] = *(const uint32_t*)&sm.m.Wh[n0 + ni * 8 + bn][bk + 8];
                bl[ni][0] = *(const uint32_t*)&sm.m.Wl[n0 + ni * 8 + bn][bk];
                bl[ni][1] = *(const uint32_t*)&sm.m.Wl[n0 + ni * 8 + bn][bk + 8];
            }
            #pragma unroll
            for (int mi = 0; mi < 2; mi++)
                #pragma unroll
                for (int ni = 0; ni < 4; ni++) {
                    mma_bf16(acc[mi][ni], ah[mi], bh[ni]);
                    mma_bf16(acc[mi][ni], ah[mi], bl[ni]);
                    mma_bf16(acc[mi][ni], al[mi], bh[ni]);
                }
        }
        __syncthreads();
    }

    // ---- epilogue: stage through smem ----
    {
        int g  = lane >> 2;
        int tc = lane & 3;
        #pragma unroll
        for (int mi = 0; mi < 2; mi++)
            #pragma unroll
            for (int ni = 0; ni < 4; ni++) {
                int m = m0 + mi * 16 + g;
                int n = n0 + ni * 8 + tc * 2;
                sm.stage[n][m]         = acc[mi][ni][0];
                sm.stage[n + 1][m]     = acc[mi][ni][1];
                sm.stage[n][m + 8]     = acc[mi][ni][2];
                sm.stage[n + 1][m + 8] = acc[mi][ni][3];
            }
    }
    __syncthreads();
    {
        int p    = t & 127;
        int half = t >> 7;
        #pragma unroll
        for (int oi = 0; oi < 32; oi++) {
            int o = half * 32 + oi;
            out[((size_t)b * COUT + o) * L_ + lo0 + p] = sm.stage[o][p] + bsh[o];
        }
    }
}

// ---------------------------------------------------------------------------
extern "C" void kernel_launch(void* const* d_in, const int* in_sizes, int n_in,
                              void* d_out, int out_size) {
    const float* x      = (const float*)d_in[0];
    const float* off    = (const float*)d_in[1];
    const float* weight = (const float*)d_in[2];
    const float* bias   = (const float*)d_in[3];
    float* out          = (float*)d_out;

    dim3 tg(L_ / 32, CIN / 32, B_);
    transpose_x_kernel<<<tg, dim3(32, 8)>>>(x);
    wsplit_kernel<<<KK * CIN, COUT>>>(weight);

    dim3 mg(L_ / TP, B_);
    deform_main_kernel<<<mg, 256>>>(off, bias, out);
}

// round 4
// speedup vs baseline: 2.0821x; 1.4221x over previous
#include <cuda_runtime.h>
#include <cuda_fp16.h>
#include <cstdint>

// Problem constants
#define B_    8
#define CIN   64
#define COUT  64
#define L_    16384
#define KK    5
#define PAD_  2
#define LP    (L_ + 2*PAD_)
#define TP    128
#define NTHR  256

// x slice in smem
#define SPAN     160
#define SPAN_LO  16
#define XS_STR   66        // floats per row (odd*2 -> conflict-friendly, 8B-aligned pairs)

// smem byte offsets
#define SM_XS    0                          // 160*66*4 = 42240
#define SM_A     42240                      // 2 bufs * 128 * 80B = 20480
#define SM_W     62720                      // 2 bufs * 2 splits * 64 * 80B = 20480
#define SM_FR    83200                      // 5*128*4 = 2560
#define SM_J0    85760                      // 2560
#define SM_J1    88320                      // 2560
#define SM_BS    90880                      // 256
#define SM_TOTAL 91136
#define A_BUF_STRIDE 10240
#define W_BUF_STRIDE 10240
#define W_SPL_STRIDE 5120
#define STAGE_STR 132                       // epilogue stage stride (floats), reuses SM_XS

// Preprocessed split weights: [k][o][c]
__device__ __half g_wh[KK * COUT * CIN];
__device__ __half g_wl[KK * COUT * CIN];

// ---------------------------------------------------------------------------
// weight (o,c,k) -> split fp16 hi/lo at [k][o][c]
// ---------------------------------------------------------------------------
__global__ void wsplit_kernel(const float* __restrict__ w) {
    int q = blockIdx.x;          // q = k*64 + o
    int c = threadIdx.x;         // 0..63
    int k = q >> 6;
    int o = q & 63;
    float v = w[o * (CIN * KK) + c * KK + k];
    __half hi = __float2half_rn(v);
    __half lo = __float2half_rn(v - __half2float(hi));
    g_wh[q * CIN + c] = hi;
    g_wl[q * CIN + c] = lo;
}

// ---------------------------------------------------------------------------
__device__ __forceinline__ void ldm_x4(uint32_t& r0, uint32_t& r1, uint32_t& r2, uint32_t& r3,
                                       const void* p) {
    uint32_t a = (uint32_t)__cvta_generic_to_shared(p);
    asm volatile("ldmatrix.sync.aligned.m8n8.x4.shared.b16 {%0,%1,%2,%3}, [%4];"
                 : "=r"(r0), "=r"(r1), "=r"(r2), "=r"(r3) : "r"(a));
}

__device__ __forceinline__ void mma_fp16(float* c, const uint32_t* a, const uint32_t* b) {
    asm volatile(
        "mma.sync.aligned.m16n8k16.row.col.f32.f16.f16.f32 "
        "{%0,%1,%2,%3}, {%4,%5,%6,%7}, {%8,%9}, {%0,%1,%2,%3};"
        : "+f"(c[0]), "+f"(c[1]), "+f"(c[2]), "+f"(c[3])
        : "r"(a[0]), "r"(a[1]), "r"(a[2]), "r"(a[3]), "r"(b[0]), "r"(b[1]));
}

// ---------------------------------------------------------------------------
// build A chunk (128 pos x 32 ch, fp16) for chunk ch into buffer ch&1
// ---------------------------------------------------------------------------
__device__ __forceinline__ void build_chunk(char* sm, const float* __restrict__ xb,
                                            int base, int ch, int t) {
    const int k  = ch >> 1;
    const int c0 = (ch & 1) * 32;
    const int cp = t & 15;       // channel pair within chunk
    const int pb = t >> 4;       // 0..15
    const float* xs  = (const float*)(sm + SM_XS);
    const float* fr  = (const float*)(sm + SM_FR);
    const int*   j0a = (const int*)(sm + SM_J0);
    const int*   j1a = (const int*)(sm + SM_J1);
    char* A = sm + SM_A + (ch & 1) * A_BUF_STRIDE;
    const int cabs = c0 + cp * 2;

    #pragma unroll
    for (int pi = 0; pi < 8; pi++) {
        int p = pb + pi * 16;
        float f = fr[k * TP + p];
        int j0  = j0a[k * TP + p];
        int j1  = j1a[k * TP + p];
        float2 g0, g1;
        if ((unsigned)j0 < SPAN) {
            g0 = *(const float2*)(xs + j0 * XS_STR + cabs);
        } else {                                  // cold path (never statistically)
            int ja = j0 + base;
            g0.x = xb[(size_t)cabs * L_ + ja];
            g0.y = xb[(size_t)(cabs + 1) * L_ + ja];
        }
        if ((unsigned)j1 < SPAN) {
            g1 = *(const float2*)(xs + j1 * XS_STR + cabs);
        } else {
            int ja = j1 + base;
            g1.x = xb[(size_t)cabs * L_ + ja];
            g1.y = xb[(size_t)(cabs + 1) * L_ + ja];
        }
        float v0 = fmaf(f, g1.x - g0.x, g0.x);
        float v1 = fmaf(f, g1.y - g0.y, g0.y);
        *(__half2*)(A + p * 80 + cp * 4) = __floats2half2_rn(v0, v1);
    }
}

// ---------------------------------------------------------------------------
// prefetch W chunk (64 o x 32 ch, hi & lo) for chunk ch into buffer ch&1
// ---------------------------------------------------------------------------
__device__ __forceinline__ void load_wchunk(char* sm, int ch, int t) {
    const int k  = ch >> 1;
    const int c0 = (ch & 1) * 32;
    int o = t >> 2;
    int q = t & 3;
    const uint4* srch = (const uint4*)(g_wh + (k * 64 + o) * CIN + c0 + q * 8);
    const uint4* srcl = (const uint4*)(g_wl + (k * 64 + o) * CIN + c0 + q * 8);
    char* W = sm + SM_W + (ch & 1) * W_BUF_STRIDE;
    *(uint4*)(W + o * 80 + q * 16)                = *srch;
    *(uint4*)(W + W_SPL_STRIDE + o * 80 + q * 16) = *srcl;
}

// ---------------------------------------------------------------------------
// Main fused kernel
// ---------------------------------------------------------------------------
__global__ __launch_bounds__(NTHR, 2) void deform_main_kernel(
    const float* __restrict__ x,      // (B, CIN, L)
    const float* __restrict__ off,    // (B, 1, L, K)
    const float* __restrict__ bias,   // (COUT)
    float* __restrict__ out)          // (B, COUT, L)
{
    extern __shared__ char sm[];

    const int b    = blockIdx.y;
    const int lo0  = blockIdx.x * TP;
    const int t    = threadIdx.x;
    const int lane = t & 31;
    const int wid  = t >> 5;
    const int base = lo0 - SPAN_LO;

    const float* xb = x + (size_t)b * CIN * L_;

    float* fr  = (float*)(sm + SM_FR);
    int*   j0a = (int*)(sm + SM_J0);
    int*   j1a = (int*)(sm + SM_J1);
    float* bsh = (float*)(sm + SM_BS);
    float* xs  = (float*)(sm + SM_XS);

    if (t < COUT) bsh[t] = bias[t];

    // ---- x slice load: [q][c], coalesced LDG along q ----
    if (base >= 0 && base + SPAN <= L_) {
        for (int idx = t; idx < CIN * SPAN; idx += NTHR) {
            int c = idx / SPAN;
            int q = idx - c * SPAN;
            xs[q * XS_STR + c] = xb[(size_t)c * L_ + base + q];
        }
    } else {
        for (int idx = t; idx < CIN * SPAN; idx += NTHR) {
            int c = idx / SPAN;
            int q = idx - c * SPAN;
            int ja = base + q;
            ja = min(max(ja, 0), L_ - 1);        // unused entries, any value
            xs[q * XS_STR + c] = xb[(size_t)c * L_ + ja];
        }
    }

    // ---- interp params ----
    const float* offb = off + ((size_t)b * L_ + lo0) * KK;
    for (int idx = t; idx < TP * KK; idx += NTHR) {
        int p = idx / KK;
        int k = idx % KK;
        float T = (float)(lo0 + p + k) + offb[idx];
        T = fminf(fmaxf(T, 0.0f), (float)(LP - 1));
        int i0 = (int)floorf(T);
        i0 = min(max(i0, 0), LP - 2);
        float f = T - (float)i0;
        int j0 = i0 - PAD_;
        int j1 = i0 + 1 - PAD_;
        j0 = (j0 < 0) ? -j0 : j0;
        j1 = (j1 < 0) ? -j1 : j1;
        if (j0 >= L_) j0 = 2 * L_ - 2 - j0;
        if (j1 >= L_) j1 = 2 * L_ - 2 - j1;
        fr[k * TP + p]  = f;
        j0a[k * TP + p] = j0 - base;             // slice-relative
        j1a[k * TP + p] = j1 - base;
    }

    load_wchunk(sm, 0, t);
    __syncthreads();

    build_chunk(sm, xb, base, 0, t);
    __syncthreads();

    // warp tiling: 4 (M) x 2 (N), warp tile 32x32
    const int m0 = (wid & 3) * 32;
    const int n0 = (wid >> 2) * 32;

    float acc[2][4][4];
    #pragma unroll
    for (int i = 0; i < 2; i++)
        #pragma unroll
        for (int j = 0; j < 4; j++)
            #pragma unroll
            for (int r = 0; r < 4; r++) acc[i][j][r] = 0.0f;

    for (int ch = 0; ch < 10; ch++) {
        if (ch < 9) {
            load_wchunk(sm, ch + 1, t);
            build_chunk(sm, xb, base, ch + 1, t);
        }

        // ---- MMA on chunk ch ----
        const char* A = sm + SM_A + (ch & 1) * A_BUF_STRIDE;
        const char* W = sm + SM_W + (ch & 1) * W_BUF_STRIDE;
        #pragma unroll
        for (int ks = 0; ks < 2; ks++) {
            uint32_t a[2][4], bh[4][2], bl[4][2];
            int arow = lane & 15;
            int acolB = (ks * 16 + (lane >> 4) * 8) * 2;
            #pragma unroll
            for (int mi = 0; mi < 2; mi++)
                ldm_x4(a[mi][0], a[mi][1], a[mi][2], a[mi][3],
                       A + (m0 + mi * 16 + arow) * 80 + acolB);
            int bn = lane >> 2;
            int bkB = (ks * 16 + (lane & 3) * 2) * 2;
            #pragma unroll
            for (int ni = 0; ni < 4; ni++) {
                const char* rowh = W + (n0 + ni * 8 + bn) * 80 + bkB;
                const char* rowl = rowh + W_SPL_STRIDE;
                bh[ni][0] = *(const uint32_t*)rowh;
                bh[ni][1] = *(const uint32_t*)(rowh + 16);
                bl[ni][0] = *(const uint32_t*)rowl;
                bl[ni][1] = *(const uint32_t*)(rowl + 16);
            }
            #pragma unroll
            for (int mi = 0; mi < 2; mi++)
                #pragma unroll
                for (int ni = 0; ni < 4; ni++) {
                    mma_fp16(acc[mi][ni], a[mi], bh[ni]);
                    mma_fp16(acc[mi][ni], a[mi], bl[ni]);
                }
        }
        __syncthreads();
    }

    // ---- epilogue: stage through smem (reuses xs region) for coalesced stores ----
    float* stage = (float*)(sm + SM_XS);       // [COUT][STAGE_STR]
    {
        int g  = lane >> 2;
        int tc = lane & 3;
        #pragma unroll
        for (int mi = 0; mi < 2; mi++)
            #pragma unroll
            for (int ni = 0; ni < 4; ni++) {
                int m = m0 + mi * 16 + g;
                int n = n0 + ni * 8 + tc * 2;
                stage[n * STAGE_STR + m]           = acc[mi][ni][0];
                stage[(n + 1) * STAGE_STR + m]     = acc[mi][ni][1];
                stage[n * STAGE_STR + m + 8]       = acc[mi][ni][2];
                stage[(n + 1) * STAGE_STR + m + 8] = acc[mi][ni][3];
            }
    }
    __syncthreads();
    {
        int p    = t & 127;
        int half = t >> 7;
        #pragma unroll
        for (int oi = 0; oi < 32; oi++) {
            int o = half * 32 + oi;
            out[((size_t)b * COUT + o) * L_ + lo0 + p] = stage[o * STAGE_STR + p] + bsh[o];
        }
    }
}

// ---------------------------------------------------------------------------
extern "C" void kernel_launch(void* const* d_in, const int* in_sizes, int n_in,
                              void* d_out, int out_size) {
    const float* x      = (const float*)d_in[0];
    const float* off    = (const float*)d_in[1];
    const float* weight = (const float*)d_in[2];
    const float* bias   = (const float*)d_in[3];
    float* out          = (float*)d_out;

    static bool attr_set = false;
    if (!attr_set) {
        cudaFuncSetAttribute(deform_main_kernel,
                             cudaFuncAttributeMaxDynamicSharedMemorySize, SM_TOTAL);
        attr_set = true;
    }

    wsplit_kernel<<<KK * COUT, CIN>>>(weight);

    dim3 mg(L_ / TP, B_);
    deform_main_kernel<<<mg, NTHR, SM_TOTAL>>>(x, off, bias, out);
}

// round 5
// speedup vs baseline: 2.8858x; 1.3860x over previous
#include <cuda_runtime.h>
#include <cuda_fp16.h>
#include <cstdint>

// Problem constants
#define B_    8
#define CIN   64
#define COUT  64
#define L_    16384
#define KK    5
#define PAD_  2
#define LP    (L_ + 2*PAD_)
#define TP    128
#define NTHR  256

// x slice in smem (fp16)
#define SPAN     160
#define SPAN_LO  16
#define XSH      68        // halves per row (136B; rows shift 2 banks)

// smem byte offsets
#define SM_XS    0                          // 160*68*2 = 21760
#define SM_A     21760                      // 2 bufs * 128 * 80B = 20480
#define SM_W     42240                      // 2 bufs * 64 * 80B = 10240
#define SM_FR    52480                      // 5*128*2 (half) = 1280
#define SM_JJ    53760                      // 5*128*4 packed = 2560
#define SM_BS    56320                      // 256
#define SM_TOTAL 56576
#define A_BUF_STRIDE 10240
#define W_BUF_STRIDE 5120
#define STAGE_STR 132                       // epilogue stage stride (floats), reuses XS+A

// Preprocessed fp16 weights: [k][o][c]
__device__ __half g_w[KK * COUT * CIN];

// ---------------------------------------------------------------------------
__global__ void wconv_kernel(const float* __restrict__ w) {
    int q = blockIdx.x;          // q = k*64 + o
    int c = threadIdx.x;
    int k = q >> 6;
    int o = q & 63;
    g_w[q * CIN + c] = __float2half_rn(w[o * (CIN * KK) + c * KK + k]);
}

// ---------------------------------------------------------------------------
__device__ __forceinline__ void ldm_x4(uint32_t& r0, uint32_t& r1, uint32_t& r2, uint32_t& r3,
                                       const void* p) {
    uint32_t a = (uint32_t)__cvta_generic_to_shared(p);
    asm volatile("ldmatrix.sync.aligned.m8n8.x4.shared.b16 {%0,%1,%2,%3}, [%4];"
                 : "=r"(r0), "=r"(r1), "=r"(r2), "=r"(r3) : "r"(a));
}

__device__ __forceinline__ void mma_fp16(float* c, const uint32_t* a, const uint32_t* b) {
    asm volatile(
        "mma.sync.aligned.m16n8k16.row.col.f32.f16.f16.f32 "
        "{%0,%1,%2,%3}, {%4,%5,%6,%7}, {%8,%9}, {%0,%1,%2,%3};"
        : "+f"(c[0]), "+f"(c[1]), "+f"(c[2]), "+f"(c[3])
        : "r"(a[0]), "r"(a[1]), "r"(a[2]), "r"(a[3]), "r"(b[0]), "r"(b[1]));
}

// ---------------------------------------------------------------------------
// build A chunk (128 pos x 32 ch, fp16) for chunk ch into buffer ch&1
// ---------------------------------------------------------------------------
__device__ __forceinline__ void build_chunk(char* sm, const float* __restrict__ xb,
                                            int base, int ch, int t) {
    const int k  = ch >> 1;
    const int c0 = (ch & 1) * 32;
    const int cp = t & 15;
    const int pb = t >> 4;
    const __half*    xs  = (const __half*)(sm + SM_XS);
    const __half*    fr  = (const __half*)(sm + SM_FR);
    const uint32_t*  jja = (const uint32_t*)(sm + SM_JJ);
    char* A = sm + SM_A + (ch & 1) * A_BUF_STRIDE;
    const int cabs = c0 + cp * 2;

    #pragma unroll
    for (int pi = 0; pi < 8; pi++) {
        int p = pb + pi * 16;
        float f = __half2float(fr[k * TP + p]);
        uint32_t jj = jja[k * TP + p];
        int j0 = (int)(jj & 0xFFFF);
        int j1 = (int)(jj >> 16);
        float2 g0, g1;
        if ((unsigned)j0 < SPAN) {
            g0 = __half22float2(*(const __half2*)(xs + j0 * XSH + cabs));
        } else {                                  // statistically never
            int ja = j0 + base - 65536 * (j0 >> 15);   // j0 stored mod 2^16; slice-rel range small
            ja = j0 + base;                             // (j values fit in [0,SPAN) or fallback below)
            ja = min(max(ja, 0), L_ - 1);
            g0.x = xb[(size_t)cabs * L_ + ja];
            g0.y = xb[(size_t)(cabs + 1) * L_ + ja];
        }
        if ((unsigned)j1 < SPAN) {
            g1 = __half22float2(*(const __half2*)(xs + j1 * XSH + cabs));
        } else {
            int ja = j1 + base;
            ja = min(max(ja, 0), L_ - 1);
            g1.x = xb[(size_t)cabs * L_ + ja];
            g1.y = xb[(size_t)(cabs + 1) * L_ + ja];
        }
        float v0 = fmaf(f, g1.x - g0.x, g0.x);
        float v1 = fmaf(f, g1.y - g0.y, g0.y);
        *(__half2*)(A + p * 80 + cp * 4) = __floats2half2_rn(v0, v1);
    }
}

// ---------------------------------------------------------------------------
__device__ __forceinline__ void load_wchunk(char* sm, int ch, int t) {
    const int k  = ch >> 1;
    const int c0 = (ch & 1) * 32;
    int o = t >> 2;
    int q = t & 3;
    const uint4* src = (const uint4*)(g_w + (k * 64 + o) * CIN + c0 + q * 8);
    char* W = sm + SM_W + (ch & 1) * W_BUF_STRIDE;
    *(uint4*)(W + o * 80 + q * 16) = *src;
}

// ---------------------------------------------------------------------------
__global__ __launch_bounds__(NTHR, 3) void deform_main_kernel(
    const float* __restrict__ x,
    const float* __restrict__ off,
    const float* __restrict__ bias,
    float* __restrict__ out)
{
    extern __shared__ char sm[];

    const int b    = blockIdx.y;
    const int lo0  = blockIdx.x * TP;
    const int t    = threadIdx.x;
    const int lane = t & 31;
    const int wid  = t >> 5;
    const int base = lo0 - SPAN_LO;

    const float* xb = x + (size_t)b * CIN * L_;

    __half*    frh = (__half*)(sm + SM_FR);
    uint32_t*  jja = (uint32_t*)(sm + SM_JJ);
    float*     bsh = (float*)(sm + SM_BS);
    __half*    xs  = (__half*)(sm + SM_XS);

    if (t < COUT) bsh[t] = bias[t];

    // ---- x slice -> fp16 smem, coalesced LDG along q ----
    {
        bool interior = (base >= 0) && (base + SPAN <= L_);
        for (int idx = t; idx < CIN * SPAN; idx += NTHR) {
            int c = idx / SPAN;
            int q = idx - c * SPAN;
            int ja = base + q;
            if (!interior) ja = min(max(ja, 0), L_ - 1);
            xs[q * XSH + c] = __float2half_rn(xb[(size_t)c * L_ + ja]);
        }
    }

    // ---- interp params ----
    const float* offb = off + ((size_t)b * L_ + lo0) * KK;
    for (int idx = t; idx < TP * KK; idx += NTHR) {
        int p = idx / KK;
        int k = idx % KK;
        float T = (float)(lo0 + p + k) + offb[idx];
        T = fminf(fmaxf(T, 0.0f), (float)(LP - 1));
        int i0 = (int)floorf(T);
        i0 = min(max(i0, 0), LP - 2);
        float f = T - (float)i0;
        int j0 = i0 - PAD_;
        int j1 = i0 + 1 - PAD_;
        j0 = (j0 < 0) ? -j0 : j0;
        j1 = (j1 < 0) ? -j1 : j1;
        if (j0 >= L_) j0 = 2 * L_ - 2 - j0;
        if (j1 >= L_) j1 = 2 * L_ - 2 - j1;
        j0 -= base;                       // slice-relative
        j1 -= base;
        // clamp into 16-bit storable range; out-of-slice handled by fallback
        j0 = min(max(j0, -32768), 32767) & 0xFFFF;
        j1 = min(max(j1, -32768), 32767);
        frh[k * TP + p] = __float2half_rn(f);
        jja[k * TP + p] = (uint32_t)j0 | ((uint32_t)j1 << 16);
    }

    load_wchunk(sm, 0, t);
    __syncthreads();

    build_chunk(sm, xb, base, 0, t);
    __syncthreads();

    // warp tiling: 4 (M) x 2 (N), warp tile 32x32
    const int m0 = (wid & 3) * 32;
    const int n0 = (wid >> 2) * 32;

    float acc[2][4][4];
    #pragma unroll
    for (int i = 0; i < 2; i++)
        #pragma unroll
        for (int j = 0; j < 4; j++)
            #pragma unroll
            for (int r = 0; r < 4; r++) acc[i][j][r] = 0.0f;

    for (int ch = 0; ch < 10; ch++) {
        if (ch < 9) {
            load_wchunk(sm, ch + 1, t);
            build_chunk(sm, xb, base, ch + 1, t);
        }

        const char* A = sm + SM_A + (ch & 1) * A_BUF_STRIDE;
        const char* W = sm + SM_W + (ch & 1) * W_BUF_STRIDE;
        #pragma unroll
        for (int ks = 0; ks < 2; ks++) {
            uint32_t a[2][4], bb[4][2];
            // A: rows m, col halves ks*16 + (lane>>4)*8
            int arow  = lane & 15;
            int acolB = (ks * 16 + (lane >> 4) * 8) * 2;
            #pragma unroll
            for (int mi = 0; mi < 2; mi++)
                ldm_x4(a[mi][0], a[mi][1], a[mi][2], a[mi][3],
                       A + (m0 + mi * 16 + arow) * 80 + acolB);
            // B via ldmatrix: [n][k] rows, non-trans
            {
                int sub = lane >> 3;          // 0..3
                int r   = lane & 7;
                int rowA = n0 + ((sub >> 1) << 3) + r;
                int colB = ks * 32 + (sub & 1) * 16;
                uint32_t r0, r1, r2, r3;
                ldm_x4(r0, r1, r2, r3, W + rowA * 80 + colB);
                bb[0][0] = r0; bb[0][1] = r1;
                bb[1][0] = r2; bb[1][1] = r3;
                ldm_x4(r0, r1, r2, r3, W + (rowA + 16) * 80 + colB);
                bb[2][0] = r0; bb[2][1] = r1;
                bb[3][0] = r2; bb[3][1] = r3;
            }
            #pragma unroll
            for (int mi = 0; mi < 2; mi++)
                #pragma unroll
                for (int ni = 0; ni < 4; ni++)
                    mma_fp16(acc[mi][ni], a[mi], bb[ni]);
        }
        __syncthreads();
    }

    // ---- epilogue: stage through smem for coalesced stores ----
    float* stage = (float*)(sm + SM_XS);       // [COUT][STAGE_STR], 33.8KB < XS+A
    {
        int g  = lane >> 2;
        int tc = lane & 3;
        #pragma unroll
        for (int mi = 0; mi < 2; mi++)
            #pragma unroll
            for (int ni = 0; ni < 4; ni++) {
                int m = m0 + mi * 16 + g;
                int n = n0 + ni * 8 + tc * 2;
                stage[n * STAGE_STR + m]           = acc[mi][ni][0];
                stage[(n + 1) * STAGE_STR + m]     = acc[mi][ni][1];
                stage[n * STAGE_STR + m + 8]       = acc[mi][ni][2];
                stage[(n + 1) * STAGE_STR + m + 8] = acc[mi][ni][3];
            }
    }
    __syncthreads();
    {
        int p    = t & 127;
        int half = t >> 7;
        #pragma unroll
        for (int oi = 0; oi < 32; oi++) {
            int o = half * 32 + oi;
            out[((size_t)b * COUT + o) * L_ + lo0 + p] = stage[o * STAGE_STR + p] + bsh[o];
        }
    }
}

// ---------------------------------------------------------------------------
extern "C" void kernel_launch(void* const* d_in, const int* in_sizes, int n_in,
                              void* d_out, int out_size) {
    const float* x      = (const float*)d_in[0];
    const float* off    = (const float*)d_in[1];
    const float* weight = (const float*)d_in[2];
    const float* bias   = (const float*)d_in[3];
    float* out          = (float*)d_out;

    static bool attr_set = false;
    if (!attr_set) {
        cudaFuncSetAttribute(deform_main_kernel,
                             cudaFuncAttributeMaxDynamicSharedMemorySize, SM_TOTAL);
        attr_set = true;
    }

    wconv_kernel<<<KK * COUT, CIN>>>(weight);

    dim3 mg(L_ / TP, B_);
    deform_main_kernel<<<mg, NTHR, SM_TOTAL>>>(x, off, bias, out);
}

// round 6
// speedup vs baseline: 3.4564x; 1.1978x over previous
#include <cuda_runtime.h>
#include <cuda_fp16.h>
#include <cstdint>

// Problem constants
#define B_    8
#define CIN   64
#define COUT  64
#define L_    16384
#define KK    5
#define PAD_  2
#define LP    (L_ + 2*PAD_)
#define TP    128
#define NTHR  256

// x slice in smem (fp16)
#define SPAN  142
#define MARG  6          // base = lo0 - MARG
#define XSH   68         // halves per row (136B)

// smem byte offsets
#define SM_XS    0                 // 142*68*2 = 19312
#define SM_A     19312             // 2 bufs * 128 rows * 128B = 32768
#define SM_W     52080             // 2 bufs * 64 rows * 128B = 16384
#define SM_PAR   68464             // 5*128*8 = 5120
#define SM_TOTAL 73584
#define A_STR    16384
#define W_STR    8192
#define STAGE_STR 132

// SW128-style swizzle of 16B units within a 128B row (o = byte offset)
#define SWZ16(col, row) ((col) ^ (((row) & 7) * 16))

// Preprocessed fp16 weights: [k][o][c]
__device__ __half g_w[KK * COUT * CIN];

// ---------------------------------------------------------------------------
__global__ void wconv_kernel(const float* __restrict__ w) {
    int q = blockIdx.x;          // q = k*64 + o
    int c = threadIdx.x;
    int k = q >> 6;
    int o = q & 63;
    g_w[q * CIN + c] = __float2half_rn(w[o * (CIN * KK) + c * KK + k]);
}

// ---------------------------------------------------------------------------
__device__ __forceinline__ void ldm_x4(uint32_t& r0, uint32_t& r1, uint32_t& r2, uint32_t& r3,
                                       const void* p) {
    uint32_t a = (uint32_t)__cvta_generic_to_shared(p);
    asm volatile("ldmatrix.sync.aligned.m8n8.x4.shared.b16 {%0,%1,%2,%3}, [%4];"
                 : "=r"(r0), "=r"(r1), "=r"(r2), "=r"(r3) : "r"(a));
}

__device__ __forceinline__ void mma_fp16(float* c, const uint32_t* a, const uint32_t* b) {
    asm volatile(
        "mma.sync.aligned.m16n8k16.row.col.f32.f16.f16.f32 "
        "{%0,%1,%2,%3}, {%4,%5,%6,%7}, {%8,%9}, {%0,%1,%2,%3};"
        : "+f"(c[0]), "+f"(c[1]), "+f"(c[2]), "+f"(c[3])
        : "r"(a[0]), "r"(a[1]), "r"(a[2]), "r"(a[3]), "r"(b[0]), "r"(b[1]));
}

// ---------------------------------------------------------------------------
// build full-tap A tile (128 pos x 64 ch, fp16, swizzled) into buffer tap&1
// ---------------------------------------------------------------------------
__device__ __forceinline__ void build_tap(char* sm, const float* __restrict__ xb,
                                          int base, int tap, int t) {
    const int cq = t & 15;          // 4 channels: 4*cq .. 4*cq+3
    const int pb = t >> 4;          // 16 position groups
    const __half* xs = (const __half*)(sm + SM_XS);
    const uint2*  par = (const uint2*)(sm + SM_PAR) + tap * TP;
    char* A = sm + SM_A + (tap & 1) * A_STR;
    const int cabs = cq * 4;

    #pragma unroll
    for (int pi = 0; pi < 8; pi++) {
        int p = pb + pi * 16;
        uint2 pr = par[p];
        int j0 = (int)(short)(pr.x & 0xFFFF);
        int j1 = (int)(short)(pr.x >> 16);
        __half2 f2 = __half2half2(__ushort_as_half((unsigned short)pr.y));
        __half2 g0a, g0b, g1a, g1b;
        if (__builtin_expect((unsigned)j0 < SPAN, 1)) {
            uint2 v = *(const uint2*)(xs + j0 * XSH + cabs);
            g0a = *(__half2*)&v.x;
            g0b = *(__half2*)&v.y;
        } else {
            int ja = min(max(j0 + base, 0), L_ - 1);
            g0a = __floats2half2_rn(xb[(size_t)cabs * L_ + ja],
                                    xb[(size_t)(cabs + 1) * L_ + ja]);
            g0b = __floats2half2_rn(xb[(size_t)(cabs + 2) * L_ + ja],
                                    xb[(size_t)(cabs + 3) * L_ + ja]);
        }
        if (__builtin_expect((unsigned)j1 < SPAN, 1)) {
            uint2 v = *(const uint2*)(xs + j1 * XSH + cabs);
            g1a = *(__half2*)&v.x;
            g1b = *(__half2*)&v.y;
        } else {
            int ja = min(max(j1 + base, 0), L_ - 1);
            g1a = __floats2half2_rn(xb[(size_t)cabs * L_ + ja],
                                    xb[(size_t)(cabs + 1) * L_ + ja]);
            g1b = __floats2half2_rn(xb[(size_t)(cabs + 2) * L_ + ja],
                                    xb[(size_t)(cabs + 3) * L_ + ja]);
        }
        __half2 va = __hfma2(f2, __hsub2(g1a, g0a), g0a);
        __half2 vb = __hfma2(f2, __hsub2(g1b, g0b), g0b);
        uint2 st;
        st.x = *(uint32_t*)&va;
        st.y = *(uint32_t*)&vb;
        *(uint2*)(A + p * 128 + SWZ16(cq * 8, p)) = st;
    }
}

// ---------------------------------------------------------------------------
// load W tap tile (64 o x 64 ch fp16, swizzled) into buffer tap&1
// ---------------------------------------------------------------------------
__device__ __forceinline__ void load_wtap(char* sm, int tap, int t) {
    char* W = sm + SM_W + (tap & 1) * W_STR;
    int o = t >> 2;
    int q = t & 3;
    #pragma unroll
    for (int h = 0; h < 2; h++) {
        int qq = q + h * 4;
        *(uint4*)(W + o * 128 + SWZ16(qq * 16, o)) =
            *(const uint4*)(g_w + (tap * 64 + o) * 64 + qq * 8);
    }
}

// ---------------------------------------------------------------------------
__global__ __launch_bounds__(NTHR, 3) void deform_main_kernel(
    const float* __restrict__ x,
    const float* __restrict__ off,
    const float* __restrict__ bias,
    float* __restrict__ out)
{
    extern __shared__ char sm[];

    const int b    = blockIdx.y;
    const int lo0  = blockIdx.x * TP;
    const int t    = threadIdx.x;
    const int lane = t & 31;
    const int wid  = t >> 5;
    const int base = lo0 - MARG;

    const float* xb = x + (size_t)b * CIN * L_;
    __half* xs = (__half*)(sm + SM_XS);
    uint2*  par = (uint2*)(sm + SM_PAR);

    // ---- x slice -> fp16 smem ----
    {
        bool interior = (base >= 0) && (base + SPAN <= L_);
        for (int idx = t; idx < CIN * SPAN; idx += NTHR) {
            int c = idx / SPAN;
            int q = idx - c * SPAN;
            int ja = base + q;
            if (!interior) ja = min(max(ja, 0), L_ - 1);
            xs[q * XSH + c] = __float2half_rn(xb[(size_t)c * L_ + ja]);
        }
    }

    // ---- interp params (packed: j0|j1<<16, f as fp16) ----
    const float* offb = off + ((size_t)b * L_ + lo0) * KK;
    for (int idx = t; idx < TP * KK; idx += NTHR) {
        int p = idx / KK;
        int k = idx % KK;
        float T = (float)(lo0 + p + k) + offb[idx];
        T = fminf(fmaxf(T, 0.0f), (float)(LP - 1));
        int i0 = (int)floorf(T);
        i0 = min(max(i0, 0), LP - 2);
        float f = T - (float)i0;
        int j0 = i0 - PAD_;
        int j1 = i0 + 1 - PAD_;
        j0 = (j0 < 0) ? -j0 : j0;
        j1 = (j1 < 0) ? -j1 : j1;
        if (j0 >= L_) j0 = 2 * L_ - 2 - j0;
        if (j1 >= L_) j1 = 2 * L_ - 2 - j1;
        j0 -= base;                       // slice-relative (fits int16)
        j1 -= base;
        uint2 pr;
        pr.x = ((uint32_t)j0 & 0xFFFF) | (((uint32_t)j1 & 0xFFFF) << 16);
        pr.y = (uint32_t)__half_as_ushort(__float2half_rn(f));
        par[k * TP + p] = pr;
    }

    load_wtap(sm, 0, t);
    __syncthreads();

    build_tap(sm, xb, base, 0, t);
    __syncthreads();

    // warp tiling: 4 (M) x 2 (N), warp tile 32x32
    const int m0 = (wid & 3) * 32;
    const int n0 = (wid >> 2) * 32;

    float acc[2][4][4];
    #pragma unroll
    for (int i = 0; i < 2; i++)
        #pragma unroll
        for (int j = 0; j < 4; j++)
            #pragma unroll
            for (int r = 0; r < 4; r++) acc[i][j][r] = 0.0f;

    for (int tap = 0; tap < KK; tap++) {
        if (tap < KK - 1) {
            load_wtap(sm, tap + 1, t);
            build_tap(sm, xb, base, tap + 1, t);
        }

        const char* A = sm + SM_A + (tap & 1) * A_STR;
        const char* W = sm + SM_W + (tap & 1) * W_STR;
        #pragma unroll
        for (int ks = 0; ks < 4; ks++) {
            uint32_t a[2][4], bb[4][2];
            // A fragments
            int arow = lane & 15;
            int acb  = ks * 32 + (lane >> 4) * 16;
            #pragma unroll
            for (int mi = 0; mi < 2; mi++) {
                int row = m0 + mi * 16 + arow;
                ldm_x4(a[mi][0], a[mi][1], a[mi][2], a[mi][3],
                       A + row * 128 + SWZ16(acb, arow));
            }
            // B fragments via non-trans ldmatrix on [n][k] rows
            {
                int sub  = lane >> 3;
                int r    = lane & 7;
                int rowA = n0 + ((sub >> 1) << 3) + r;
                int colB = ks * 32 + (sub & 1) * 16;
                uint32_t r0, r1, r2, r3;
                ldm_x4(r0, r1, r2, r3, W + rowA * 128 + SWZ16(colB, r));
                bb[0][0] = r0; bb[0][1] = r1;
                bb[1][0] = r2; bb[1][1] = r3;
                ldm_x4(r0, r1, r2, r3, W + (rowA + 16) * 128 + SWZ16(colB, r));
                bb[2][0] = r0; bb[2][1] = r1;
                bb[3][0] = r2; bb[3][1] = r3;
            }
            #pragma unroll
            for (int mi = 0; mi < 2; mi++)
                #pragma unroll
                for (int ni = 0; ni < 4; ni++)
                    mma_fp16(acc[mi][ni], a[mi], bb[ni]);
        }
        __syncthreads();
    }

    // ---- epilogue: stage through smem for coalesced stores ----
    float* stage = (float*)(sm + SM_XS);       // [COUT][STAGE_STR] = 33.8KB
    {
        int g  = lane >> 2;
        int tc = lane & 3;
        #pragma unroll
        for (int mi = 0; mi < 2; mi++)
            #pragma unroll
            for (int ni = 0; ni < 4; ni++) {
                int m = m0 + mi * 16 + g;
                int n = n0 + ni * 8 + tc * 2;
                stage[n * STAGE_STR + m]           = acc[mi][ni][0];
                stage[(n + 1) * STAGE_STR + m]     = acc[mi][ni][1];
                stage[n * STAGE_STR + m + 8]       = acc[mi][ni][2];
                stage[(n + 1) * STAGE_STR + m + 8] = acc[mi][ni][3];
            }
    }
    __syncthreads();
    {
        int p    = t & 127;
        int half = t >> 7;
        #pragma unroll
        for (int oi = 0; oi < 32; oi++) {
            int o = half * 32 + oi;
            out[((size_t)b * COUT + o) * L_ + lo0 + p] =
                stage[o * STAGE_STR + p] + __ldg(&bias[o]);
        }
    }
}

// ---------------------------------------------------------------------------
extern "C" void kernel_launch(void* const* d_in, const int* in_sizes, int n_in,
                              void* d_out, int out_size) {
    const float* x      = (const float*)d_in[0];
    const float* off    = (const float*)d_in[1];
    const float* weight = (const float*)d_in[2];
    const float* bias   = (const float*)d_in[3];
    float* out          = (float*)d_out;

    static bool attr_set = false;
    if (!attr_set) {
        cudaFuncSetAttribute(deform_main_kernel,
                             cudaFuncAttributeMaxDynamicSharedMemorySize, SM_TOTAL);
        attr_set = true;
    }

    wconv_kernel<<<KK * COUT, CIN>>>(weight);

    dim3 mg(L_ / TP, B_);
    deform_main_kernel<<<mg, NTHR, SM_TOTAL>>>(x, off, bias, out);
}

// round 8
// speedup vs baseline: 3.4694x; 1.0038x over previous
#include <cuda_runtime.h>
#include <cuda_fp16.h>
#include <cstdint>

// Problem constants
#define B_    8
#define CIN   64
#define COUT  64
#define L_    16384
#define KK    5
#define PAD_  2
#define LP    (L_ + 2*PAD_)
#define TP    128
#define NTHR  256

// x slice in smem (fp16)
#define SPAN  142
#define MARG  6          // base = lo0 - MARG
#define XSH   72         // halves per row (144B, 16B-aligned rows for LDS.128)

// smem byte offsets
#define SM_XS    0                 // 142*72*2 = 20448 -> 20480
#define SM_A     20480             // 2 bufs * 128 rows * 128B = 32768
#define SM_W     53248             // 2 bufs * 64 rows * 128B = 16384
#define SM_PAR   69632             // 5*128*8 = 5120
#define SM_TOTAL 74752
#define A_STR    16384
#define W_STR    8192
#define STAGE_STR 132

// swizzle of 16B units within a 128B row
#define SWZ16(col, row) ((col) ^ (((row) & 7) * 16))

// Preprocessed fp16 weights: [k][o][c]
__device__ __half g_w[KK * COUT * CIN];

// ---------------------------------------------------------------------------
__global__ void wconv_kernel(const float* __restrict__ w) {
    int q = blockIdx.x;          // q = k*64 + o
    int c = threadIdx.x;
    int k = q >> 6;
    int o = q & 63;
    g_w[q * CIN + c] = __float2half_rn(w[o * (CIN * KK) + c * KK + k]);
}

// ---------------------------------------------------------------------------
__device__ __forceinline__ void ldm_x4(uint32_t& r0, uint32_t& r1, uint32_t& r2, uint32_t& r3,
                                       const void* p) {
    uint32_t a = (uint32_t)__cvta_generic_to_shared(p);
    asm volatile("ldmatrix.sync.aligned.m8n8.x4.shared.b16 {%0,%1,%2,%3}, [%4];"
                 : "=r"(r0), "=r"(r1), "=r"(r2), "=r"(r3) : "r"(a));
}

__device__ __forceinline__ void mma_fp16(float* c, const uint32_t* a, const uint32_t* b) {
    asm volatile(
        "mma.sync.aligned.m16n8k16.row.col.f32.f16.f16.f32 "
        "{%0,%1,%2,%3}, {%4,%5,%6,%7}, {%8,%9}, {%0,%1,%2,%3};"
        : "+f"(c[0]), "+f"(c[1]), "+f"(c[2]), "+f"(c[3])
        : "r"(a[0]), "r"(a[1]), "r"(a[2]), "r"(a[3]), "r"(b[0]), "r"(b[1]));
}

// ---------------------------------------------------------------------------
// build full-tap A tile (128 pos x 64 ch). 8 channels/thread, LDS.128 gathers.
// ---------------------------------------------------------------------------
__device__ __forceinline__ void build_tap(char* sm, const float* __restrict__ xb,
                                          int base, int tap, int t) {
    const int cq = t & 7;           // 8 channels: 8*cq .. 8*cq+7
    const int pb = t >> 3;          // 32 position groups
    const __half* xs = (const __half*)(sm + SM_XS);
    const uint2*  par = (const uint2*)(sm + SM_PAR) + tap * TP;
    char* A = sm + SM_A + (tap & 1) * A_STR;
    const int cabs = cq * 8;
    const int swc  = SWZ16(cq * 16, pb);   // p&7 == pb&7 (pi stride 32)

    #pragma unroll
    for (int pi = 0; pi < 4; pi++) {
        int p = pb + pi * 32;
        uint2 pr = par[p];
        int j0 = (int)(short)(pr.x & 0xFFFF);
        int j1 = (int)(short)(pr.x >> 16);
        __half2 f2 = __half2half2(__ushort_as_half((unsigned short)pr.y));
        uint4 u0, u1;
        if (__builtin_expect((unsigned)j0 < SPAN, 1)) {
            u0 = *(const uint4*)(xs + j0 * XSH + cabs);
        } else {
            int ja = min(max(j0 + base, 0), L_ - 1);
            __half2 h01 = __floats2half2_rn(xb[(size_t)cabs * L_ + ja],
                                            xb[(size_t)(cabs + 1) * L_ + ja]);
            __half2 h23 = __floats2half2_rn(xb[(size_t)(cabs + 2) * L_ + ja],
                                            xb[(size_t)(cabs + 3) * L_ + ja]);
            __half2 h45 = __floats2half2_rn(xb[(size_t)(cabs + 4) * L_ + ja],
                                            xb[(size_t)(cabs + 5) * L_ + ja]);
            __half2 h67 = __floats2half2_rn(xb[(size_t)(cabs + 6) * L_ + ja],
                                            xb[(size_t)(cabs + 7) * L_ + ja]);
            u0.x = *(uint32_t*)&h01; u0.y = *(uint32_t*)&h23;
            u0.z = *(uint32_t*)&h45; u0.w = *(uint32_t*)&h67;
        }
        if (__builtin_expect((unsigned)j1 < SPAN, 1)) {
            u1 = *(const uint4*)(xs + j1 * XSH + cabs);
        } else {
            int ja = min(max(j1 + base, 0), L_ - 1);
            __half2 h01 = __floats2half2_rn(xb[(size_t)cabs * L_ + ja],
                                            xb[(size_t)(cabs + 1) * L_ + ja]);
            __half2 h23 = __floats2half2_rn(xb[(size_t)(cabs + 2) * L_ + ja],
                                            xb[(size_t)(cabs + 3) * L_ + ja]);
            __half2 h45 = __floats2half2_rn(xb[(size_t)(cabs + 4) * L_ + ja],
                                            xb[(size_t)(cabs + 5) * L_ + ja]);
            __half2 h67 = __floats2half2_rn(xb[(size_t)(cabs + 6) * L_ + ja],
                                            xb[(size_t)(cabs + 7) * L_ + ja]);
            u1.x = *(uint32_t*)&h01; u1.y = *(uint32_t*)&h23;
            u1.z = *(uint32_t*)&h45; u1.w = *(uint32_t*)&h67;
        }
        __half2 g0, g1;
        uint4 st;
        g0 = *(__half2*)&u0.x; g1 = *(__half2*)&u1.x;
        { __half2 v = __hfma2(f2, __hsub2(g1, g0), g0); st.x = *(uint32_t*)&v; }
        g0 = *(__half2*)&u0.y; g1 = *(__half2*)&u1.y;
        { __half2 v = __hfma2(f2, __hsub2(g1, g0), g0); st.y = *(uint32_t*)&v; }
        g0 = *(__half2*)&u0.z; g1 = *(__half2*)&u1.z;
        { __half2 v = __hfma2(f2, __hsub2(g1, g0), g0); st.z = *(uint32_t*)&v; }
        g0 = *(__half2*)&u0.w; g1 = *(__half2*)&u1.w;
        { __half2 v = __hfma2(f2, __hsub2(g1, g0), g0); st.w = *(uint32_t*)&v; }
        *(uint4*)(A + p * 128 + swc) = st;
    }
}

// ---------------------------------------------------------------------------
__device__ __forceinline__ void load_wtap(char* sm, int tap, int t) {
    char* W = sm + SM_W + (tap & 1) * W_STR;
    int o = t >> 2;
    int q = t & 3;
    #pragma unroll
    for (int h = 0; h < 2; h++) {
        int qq = q + h * 4;
        *(uint4*)(W + o * 128 + SWZ16(qq * 16, o)) =
            *(const uint4*)(g_w + (tap * 64 + o) * 64 + qq * 8);
    }
}

// ---------------------------------------------------------------------------
__global__ __launch_bounds__(NTHR, 3) void deform_main_kernel(
    const float* __restrict__ x,
    const float* __restrict__ off,
    const float* __restrict__ bias,
    float* __restrict__ out)
{
    extern __shared__ char sm[];

    const int b    = blockIdx.y;
    const int lo0  = blockIdx.x * TP;
    const int t    = threadIdx.x;
    const int lane = t & 31;
    const int wid  = t >> 5;
    const int base = lo0 - MARG;

    const float* xb = x + (size_t)b * CIN * L_;
    __half* xs = (__half*)(sm + SM_XS);
    uint2*  par = (uint2*)(sm + SM_PAR);

    // ---- x slice -> fp16 smem (float2 loads) ----
    {
        bool interior = (base >= 0) && (base + SPAN + 1 <= L_);
        for (int idx = t; idx < CIN * (SPAN / 2); idx += NTHR) {
            int c  = idx / (SPAN / 2);
            int qp = idx - c * (SPAN / 2);
            int q  = qp * 2;
            float2 v;
            if (interior) {
                v = *(const float2*)(xb + (size_t)c * L_ + base + q);
            } else {
                int ja0 = min(max(base + q, 0), L_ - 1);
                int ja1 = min(max(base + q + 1, 0), L_ - 1);
                v.x = xb[(size_t)c * L_ + ja0];
                v.y = xb[(size_t)c * L_ + ja1];
            }
            xs[q * XSH + c]       = __float2half_rn(v.x);
            xs[(q + 1) * XSH + c] = __float2half_rn(v.y);
        }
    }

    // ---- interp params (packed: j0|j1<<16, f as fp16) ----
    const float* offb = off + ((size_t)b * L_ + lo0) * KK;
    for (int idx = t; idx < TP * KK; idx += NTHR) {
        int p = idx / KK;
        int k = idx % KK;
        float T = (float)(lo0 + p + k) + offb[idx];
        T = fminf(fmaxf(T, 0.0f), (float)(LP - 1));
        int i0 = (int)floorf(T);
        i0 = min(max(i0, 0), LP - 2);
        float f = T - (float)i0;
        int j0 = i0 - PAD_;
        int j1 = i0 + 1 - PAD_;
        j0 = (j0 < 0) ? -j0 : j0;
        j1 = (j1 < 0) ? -j1 : j1;
        if (j0 >= L_) j0 = 2 * L_ - 2 - j0;
        if (j1 >= L_) j1 = 2 * L_ - 2 - j1;
        j0 -= base;
        j1 -= base;
        uint2 pr;
        pr.x = ((uint32_t)j0 & 0xFFFF) | (((uint32_t)j1 & 0xFFFF) << 16);
        pr.y = (uint32_t)__half_as_ushort(__float2half_rn(f));
        par[k * TP + p] = pr;
    }

    load_wtap(sm, 0, t);
    __syncthreads();

    build_tap(sm, xb, base, 0, t);
    __syncthreads();

    // warp tiling: 4 (M) x 2 (N), warp tile 32x32
    const int m0 = (wid & 3) * 32;
    const int n0 = (wid >> 2) * 32;

    float acc[2][4][4];
    #pragma unroll
    for (int i = 0; i < 2; i++)
        #pragma unroll
        for (int j = 0; j < 4; j++)
            #pragma unroll
            for (int r = 0; r < 4; r++) acc[i][j][r] = 0.0f;

    for (int tap = 0; tap < KK; tap++) {
        if (tap < KK - 1) {
            load_wtap(sm, tap + 1, t);
            build_tap(sm, xb, base, tap + 1, t);
        }

        const char* A = sm + SM_A + (tap & 1) * A_STR;
        const char* W = sm + SM_W + (tap & 1) * W_STR;
        #pragma unroll
        for (int ks = 0; ks < 4; ks++) {
            uint32_t a[2][4], bb[4][2];
            int arow = lane & 15;
            int acb  = ks * 32 + (lane >> 4) * 16;
            #pragma unroll
            for (int mi = 0; mi < 2; mi++) {
                int row = m0 + mi * 16 + arow;
                ldm_x4(a[mi][0], a[mi][1], a[mi][2], a[mi][3],
                       A + row * 128 + SWZ16(acb, arow));
            }
            {
                int sub  = lane >> 3;
                int r    = lane & 7;
                int rowA = n0 + ((sub >> 1) << 3) + r;
                int colB = ks * 32 + (sub & 1) * 16;
                uint32_t r0, r1, r2, r3;
                ldm_x4(r0, r1, r2, r3, W + rowA * 128 + SWZ16(colB, r));
                bb[0][0] = r0; bb[0][1] = r1;
                bb[1][0] = r2; bb[1][1] = r3;
                ldm_x4(r0, r1, r2, r3, W + (rowA + 16) * 128 + SWZ16(colB, r));
                bb[2][0] = r0; bb[2][1] = r1;
                bb[3][0] = r2; bb[3][1] = r3;
            }
            #pragma unroll
            for (int mi = 0; mi < 2; mi++)
                #pragma unroll
                for (int ni = 0; ni < 4; ni++)
                    mma_fp16(acc[mi][ni], a[mi], bb[ni]);
        }
        __syncthreads();
    }

    // ---- epilogue: stage through smem for coalesced stores ----
    float* stage = (float*)(sm + SM_XS);       // [COUT][STAGE_STR] = 33.8KB
    {
        int g  = lane >> 2;
        int tc = lane & 3;
        #pragma unroll
        for (int mi = 0; mi < 2; mi++)
            #pragma unroll
            for (int ni = 0; ni < 4; ni++) {
                int m = m0 + mi * 16 + g;
                int n = n0 + ni * 8 + tc * 2;
                stage[n * STAGE_STR + m]           = acc[mi][ni][0];
                stage[(n + 1) * STAGE_STR + m]     = acc[mi][ni][1];
                stage[n * STAGE_STR + m + 8]       = acc[mi][ni][2];
                stage[(n + 1) * STAGE_STR + m + 8] = acc[mi][ni][3];
            }
    }
    __syncthreads();
    {
        int p    = t & 127;
        int half = t >> 7;
        #pragma unroll
        for (int oi = 0; oi < 32; oi++) {
            int o = half * 32 + oi;
            out[((size_t)b * COUT + o) * L_ + lo0 + p] =
                stage[o * STAGE_STR + p] + __ldg(&bias[o]);
        }
    }
}

// ---------------------------------------------------------------------------
extern "C" void kernel_launch(void* const* d_in, const int* in_sizes, int n_in,
                              void* d_out, int out_size) {
    const float* x      = (const float*)d_in[0];
    const float* off    = (const float*)d_in[1];
    const float* weight = (const float*)d_in[2];
    const float* bias   = (const float*)d_in[3];
    float* out          = (float*)d_out;

    static bool attr_set = false;
    if (!attr_set) {
        cudaFuncSetAttribute(deform_main_kernel,
                             cudaFuncAttributeMaxDynamicSharedMemorySize, SM_TOTAL);
        attr_set = true;
    }

    wconv_kernel<<<KK * COUT, CIN>>>(weight);

    dim3 mg(L_ / TP, B_);
    deform_main_kernel<<<mg, NTHR, SM_TOTAL>>>(x, off, bias, out);
}

// round 9
// speedup vs baseline: 4.0318x; 1.1621x over previous
#include <cuda_runtime.h>
#include <cuda_fp16.h>
#include <cstdint>

// Problem constants
#define B_    8
#define CIN   64
#define COUT  64
#define L_    16384
#define KK    5
#define PAD_  2
#define LP    (L_ + 2*PAD_)
#define TP    128
#define NTHR  256

// x slice in smem (fp16)
#define SPAN  142
#define MARG  6          // base = lo0 - MARG
#define XSH   72         // halves per row (144B, 16B-aligned rows for LDS.128)

// smem byte offsets (single-buffered A and W -> 4 CTAs/SM)
#define SM_XS    0                 // 142*72*2 = 20448 -> 20480
#define SM_A     20480             // 128 rows * 128B = 16384
#define SM_W     36864             // 64 rows * 128B = 8192
#define SM_PAR   45056             // 5*128*8 = 5120
#define SM_TOTAL 50176
#define STAGE_STR 132              // epilogue stage (33792B, reuses XS+A)

// swizzle of 16B units within a 128B row
#define SWZ16(col, row) ((col) ^ (((row) & 7) * 16))

// Preprocessed fp16 weights: [k][o][c]
__device__ __half g_w[KK * COUT * CIN];

// ---------------------------------------------------------------------------
__global__ void wconv_kernel(const float* __restrict__ w) {
    int q = blockIdx.x;          // q = k*64 + o
    int c = threadIdx.x;
    int k = q >> 6;
    int o = q & 63;
    g_w[q * CIN + c] = __float2half_rn(w[o * (CIN * KK) + c * KK + k]);
}

// ---------------------------------------------------------------------------
__device__ __forceinline__ void ldm_x4(uint32_t& r0, uint32_t& r1, uint32_t& r2, uint32_t& r3,
                                       const void* p) {
    uint32_t a = (uint32_t)__cvta_generic_to_shared(p);
    asm volatile("ldmatrix.sync.aligned.m8n8.x4.shared.b16 {%0,%1,%2,%3}, [%4];"
                 : "=r"(r0), "=r"(r1), "=r"(r2), "=r"(r3) : "r"(a));
}

__device__ __forceinline__ void mma_fp16(float* c, const uint32_t* a, const uint32_t* b) {
    asm volatile(
        "mma.sync.aligned.m16n8k16.row.col.f32.f16.f16.f32 "
        "{%0,%1,%2,%3}, {%4,%5,%6,%7}, {%8,%9}, {%0,%1,%2,%3};"
        : "+f"(c[0]), "+f"(c[1]), "+f"(c[2]), "+f"(c[3])
        : "r"(a[0]), "r"(a[1]), "r"(a[2]), "r"(a[3]), "r"(b[0]), "r"(b[1]));
}

// ---------------------------------------------------------------------------
// build full-tap A tile (128 pos x 64 ch). 8 channels/thread, LDS.128 gathers.
// ---------------------------------------------------------------------------
__device__ __forceinline__ void build_tap(char* sm, const float* __restrict__ xb,
                                          int base, int tap, int t) {
    const int cq = t & 7;           // 8 channels: 8*cq .. 8*cq+7
    const int pb = t >> 3;          // 32 position groups
    const __half* xs = (const __half*)(sm + SM_XS);
    const uint2*  par = (const uint2*)(sm + SM_PAR) + tap * TP;
    char* A = sm + SM_A;
    const int cabs = cq * 8;
    const int swc  = SWZ16(cq * 16, pb);   // p&7 == pb&7 (pi stride 32)

    #pragma unroll
    for (int pi = 0; pi < 4; pi++) {
        int p = pb + pi * 32;
        uint2 pr = par[p];
        int j0 = (int)(short)(pr.x & 0xFFFF);
        int j1 = (int)(short)(pr.x >> 16);
        __half2 f2 = __half2half2(__ushort_as_half((unsigned short)pr.y));
        uint4 u0, u1;
        if (__builtin_expect((unsigned)j0 < SPAN, 1)) {
            u0 = *(const uint4*)(xs + j0 * XSH + cabs);
        } else {
            int ja = min(max(j0 + base, 0), L_ - 1);
            __half2 h01 = __floats2half2_rn(xb[(size_t)cabs * L_ + ja],
                                            xb[(size_t)(cabs + 1) * L_ + ja]);
            __half2 h23 = __floats2half2_rn(xb[(size_t)(cabs + 2) * L_ + ja],
                                            xb[(size_t)(cabs + 3) * L_ + ja]);
            __half2 h45 = __floats2half2_rn(xb[(size_t)(cabs + 4) * L_ + ja],
                                            xb[(size_t)(cabs + 5) * L_ + ja]);
            __half2 h67 = __floats2half2_rn(xb[(size_t)(cabs + 6) * L_ + ja],
                                            xb[(size_t)(cabs + 7) * L_ + ja]);
            u0.x = *(uint32_t*)&h01; u0.y = *(uint32_t*)&h23;
            u0.z = *(uint32_t*)&h45; u0.w = *(uint32_t*)&h67;
        }
        if (__builtin_expect((unsigned)j1 < SPAN, 1)) {
            u1 = *(const uint4*)(xs + j1 * XSH + cabs);
        } else {
            int ja = min(max(j1 + base, 0), L_ - 1);
            __half2 h01 = __floats2half2_rn(xb[(size_t)cabs * L_ + ja],
                                            xb[(size_t)(cabs + 1) * L_ + ja]);
            __half2 h23 = __floats2half2_rn(xb[(size_t)(cabs + 2) * L_ + ja],
                                            xb[(size_t)(cabs + 3) * L_ + ja]);
            __half2 h45 = __floats2half2_rn(xb[(size_t)(cabs + 4) * L_ + ja],
                                            xb[(size_t)(cabs + 5) * L_ + ja]);
            __half2 h67 = __floats2half2_rn(xb[(size_t)(cabs + 6) * L_ + ja],
                                            xb[(size_t)(cabs + 7) * L_ + ja]);
            u1.x = *(uint32_t*)&h01; u1.y = *(uint32_t*)&h23;
            u1.z = *(uint32_t*)&h45; u1.w = *(uint32_t*)&h67;
        }
        __half2 g0, g1;
        uint4 st;
        g0 = *(__half2*)&u0.x; g1 = *(__half2*)&u1.x;
        { __half2 v = __hfma2(f2, __hsub2(g1, g0), g0); st.x = *(uint32_t*)&v; }
        g0 = *(__half2*)&u0.y; g1 = *(__half2*)&u1.y;
        { __half2 v = __hfma2(f2, __hsub2(g1, g0), g0); st.y = *(uint32_t*)&v; }
        g0 = *(__half2*)&u0.z; g1 = *(__half2*)&u1.z;
        { __half2 v = __hfma2(f2, __hsub2(g1, g0), g0); st.z = *(uint32_t*)&v; }
        g0 = *(__half2*)&u0.w; g1 = *(__half2*)&u1.w;
        { __half2 v = __hfma2(f2, __hsub2(g1, g0), g0); st.w = *(uint32_t*)&v; }
        *(uint4*)(A + p * 128 + swc) = st;
    }
}

// ---------------------------------------------------------------------------
__device__ __forceinline__ void load_wtap(char* sm, int tap, int t) {
    char* W = sm + SM_W;
    int o = t >> 2;
    int q = t & 3;
    #pragma unroll
    for (int h = 0; h < 2; h++) {
        int qq = q + h * 4;
        *(uint4*)(W + o * 128 + SWZ16(qq * 16, o)) =
            *(const uint4*)(g_w + (tap * 64 + o) * 64 + qq * 8);
    }
}

// ---------------------------------------------------------------------------
__global__ __launch_bounds__(NTHR, 4) void deform_main_kernel(
    const float* __restrict__ x,
    const float* __restrict__ off,
    const float* __restrict__ bias,
    float* __restrict__ out)
{
    extern __shared__ char sm[];

    const int b    = blockIdx.y;
    const int lo0  = blockIdx.x * TP;
    const int t    = threadIdx.x;
    const int lane = t & 31;
    const int wid  = t >> 5;
    const int base = lo0 - MARG;

    const float* xb = x + (size_t)b * CIN * L_;
    __half* xs = (__half*)(sm + SM_XS);
    uint2*  par = (uint2*)(sm + SM_PAR);

    // ---- x slice -> fp16 smem (float2 loads) ----
    {
        bool interior = (base >= 0) && (base + SPAN + 1 <= L_);
        for (int idx = t; idx < CIN * (SPAN / 2); idx += NTHR) {
            int c  = idx / (SPAN / 2);
            int qp = idx - c * (SPAN / 2);
            int q  = qp * 2;
            float2 v;
            if (interior) {
                v = *(const float2*)(xb + (size_t)c * L_ + base + q);
            } else {
                int ja0 = min(max(base + q, 0), L_ - 1);
                int ja1 = min(max(base + q + 1, 0), L_ - 1);
                v.x = xb[(size_t)c * L_ + ja0];
                v.y = xb[(size_t)c * L_ + ja1];
            }
            xs[q * XSH + c]       = __float2half_rn(v.x);
            xs[(q + 1) * XSH + c] = __float2half_rn(v.y);
        }
    }

    // ---- interp params (packed: j0|j1<<16, f as fp16) ----
    const float* offb = off + ((size_t)b * L_ + lo0) * KK;
    for (int idx = t; idx < TP * KK; idx += NTHR) {
        int p = idx / KK;
        int k = idx % KK;
        float T = (float)(lo0 + p + k) + offb[idx];
        T = fminf(fmaxf(T, 0.0f), (float)(LP - 1));
        int i0 = (int)floorf(T);
        i0 = min(max(i0, 0), LP - 2);
        float f = T - (float)i0;
        int j0 = i0 - PAD_;
        int j1 = i0 + 1 - PAD_;
        j0 = (j0 < 0) ? -j0 : j0;
        j1 = (j1 < 0) ? -j1 : j1;
        if (j0 >= L_) j0 = 2 * L_ - 2 - j0;
        if (j1 >= L_) j1 = 2 * L_ - 2 - j1;
        j0 -= base;
        j1 -= base;
        uint2 pr;
        pr.x = ((uint32_t)j0 & 0xFFFF) | (((uint32_t)j1 & 0xFFFF) << 16);
        pr.y = (uint32_t)__half_as_ushort(__float2half_rn(f));
        par[k * TP + p] = pr;
    }
    __syncthreads();

    // warp tiling: 4 (M) x 2 (N), warp tile 32x32
    const int m0 = (wid & 3) * 32;
    const int n0 = (wid >> 2) * 32;

    float acc[2][4][4];
    #pragma unroll
    for (int i = 0; i < 2; i++)
        #pragma unroll
        for (int j = 0; j < 4; j++)
            #pragma unroll
            for (int r = 0; r < 4; r++) acc[i][j][r] = 0.0f;

    for (int tap = 0; tap < KK; tap++) {
        load_wtap(sm, tap, t);
        build_tap(sm, xb, base, tap, t);
        __syncthreads();

        const char* A = sm + SM_A;
        const char* W = sm + SM_W;
        #pragma unroll
        for (int ks = 0; ks < 4; ks++) {
            uint32_t a[2][4], bb[4][2];
            int arow = lane & 15;
            int acb  = ks * 32 + (lane >> 4) * 16;
            #pragma unroll
            for (int mi = 0; mi < 2; mi++) {
                int row = m0 + mi * 16 + arow;
                ldm_x4(a[mi][0], a[mi][1], a[mi][2], a[mi][3],
                       A + row * 128 + SWZ16(acb, arow));
            }
            {
                int sub  = lane >> 3;
                int r    = lane & 7;
                int rowA = n0 + ((sub >> 1) << 3) + r;
                int colB = ks * 32 + (sub & 1) * 16;
                uint32_t r0, r1, r2, r3;
                ldm_x4(r0, r1, r2, r3, W + rowA * 128 + SWZ16(colB, r));
                bb[0][0] = r0; bb[0][1] = r1;
                bb[1][0] = r2; bb[1][1] = r3;
                ldm_x4(r0, r1, r2, r3, W + (rowA + 16) * 128 + SWZ16(colB, r));
                bb[2][0] = r0; bb[2][1] = r1;
                bb[3][0] = r2; bb[3][1] = r3;
            }
            #pragma unroll
            for (int mi = 0; mi < 2; mi++)
                #pragma unroll
                for (int ni = 0; ni < 4; ni++)
                    mma_fp16(acc[mi][ni], a[mi], bb[ni]);
        }
        __syncthreads();
    }

    // ---- epilogue: stage through smem for coalesced stores ----
    float* stage = (float*)(sm + SM_XS);       // [COUT][STAGE_STR] = 33.8KB
    {
        int g  = lane >> 2;
        int tc = lane & 3;
        #pragma unroll
        for (int mi = 0; mi < 2; mi++)
            #pragma unroll
            for (int ni = 0; ni < 4; ni++) {
                int m = m0 + mi * 16 + g;
                int n = n0 + ni * 8 + tc * 2;
                stage[n * STAGE_STR + m]           = acc[mi][ni][0];
                stage[(n + 1) * STAGE_STR + m]     = acc[mi][ni][1];
                stage[n * STAGE_STR + m + 8]       = acc[mi][ni][2];
                stage[(n + 1) * STAGE_STR + m + 8] = acc[mi][ni][3];
            }
    }
    __syncthreads();
    {
        int p    = t & 127;
        int half = t >> 7;
        #pragma unroll
        for (int oi = 0; oi < 32; oi++) {
            int o = half * 32 + oi;
            out[((size_t)b * COUT + o) * L_ + lo0 + p] =
                stage[o * STAGE_STR + p] + __ldg(&bias[o]);
        }
    }
}

// ---------------------------------------------------------------------------
extern "C" void kernel_launch(void* const* d_in, const int* in_sizes, int n_in,
                              void* d_out, int out_size) {
    const float* x      = (const float*)d_in[0];
    const float* off    = (const float*)d_in[1];
    const float* weight = (const float*)d_in[2];
    const float* bias   = (const float*)d_in[3];
    float* out          = (float*)d_out;

    static bool attr_set = false;
    if (!attr_set) {
        cudaFuncSetAttribute(deform_main_kernel,
                             cudaFuncAttributeMaxDynamicSharedMemorySize, SM_TOTAL);
        attr_set = true;
    }

    wconv_kernel<<<KK * COUT, CIN>>>(weight);

    dim3 mg(L_ / TP, B_);
    deform_main_kernel<<<mg, NTHR, SM_TOTAL>>>(x, off, bias, out);
}

// round 11
// speedup vs baseline: 4.1034x; 1.0178x over previous
#include <cuda_runtime.h>
#include <cuda_fp16.h>
#include <cstdint>

// Problem constants
#define B_    8
#define CIN   64
#define COUT  64
#define L_    16384
#define KK    5
#define PAD_  2
#define LP    (L_ + 2*PAD_)
#define TP    128
#define NTHR  256

// x slice in smem (fp16)
#define SPAN  142
#define MARG  6          // base = lo0 - MARG
#define XSH   72         // halves per row (144B, 16B-aligned rows for LDS.128)

// smem byte offsets (single-buffered A and W -> 4 CTAs/SM)
#define SM_XS    0                 // 142*72*2 = 20448 -> 20480
#define SM_A     20480             // 128 rows * 128B = 16384
#define SM_W     36864             // 64 rows * 128B = 8192
#define SM_PAR   45056             // 5*128*8 = 5120
#define SM_TOTAL 50176

// swizzle of 16B units within a 128B row
#define SWZ16(col, row) ((col) ^ (((row) & 7) * 16))

// Preprocessed fp16 weights: [k][o][c]
__device__ __half g_w[KK * COUT * CIN];

// ---------------------------------------------------------------------------
__global__ void wconv_kernel(const float* __restrict__ w) {
    int q = blockIdx.x;          // q = k*64 + o
    int c = threadIdx.x;
    int k = q >> 6;
    int o = q & 63;
    g_w[q * CIN + c] = __float2half_rn(w[o * (CIN * KK) + c * KK + k]);
}

// ---------------------------------------------------------------------------
__device__ __forceinline__ void ldm_x4(uint32_t& r0, uint32_t& r1, uint32_t& r2, uint32_t& r3,
                                       const void* p) {
    uint32_t a = (uint32_t)__cvta_generic_to_shared(p);
    asm volatile("ldmatrix.sync.aligned.m8n8.x4.shared.b16 {%0,%1,%2,%3}, [%4];"
                 : "=r"(r0), "=r"(r1), "=r"(r2), "=r"(r3) : "r"(a));
}

__device__ __forceinline__ void mma_fp16(float* c, const uint32_t* a, const uint32_t* b) {
    asm volatile(
        "mma.sync.aligned.m16n8k16.row.col.f32.f16.f16.f32 "
        "{%0,%1,%2,%3}, {%4,%5,%6,%7}, {%8,%9}, {%0,%1,%2,%3};"
        : "+f"(c[0]), "+f"(c[1]), "+f"(c[2]), "+f"(c[3])
        : "r"(a[0]), "r"(a[1]), "r"(a[2]), "r"(a[3]), "r"(b[0]), "r"(b[1]));
}

// ---------------------------------------------------------------------------
// build full-tap A tile (128 pos x 64 ch). 8 channels/thread, LDS.128 gathers.
// ---------------------------------------------------------------------------
__device__ __forceinline__ void build_tap(char* sm, const float* __restrict__ xb,
                                          int base, int tap, int t) {
    const int cq = t & 7;           // 8 channels: 8*cq .. 8*cq+7
    const int pb = t >> 3;          // 32 position groups
    const __half* xs = (const __half*)(sm + SM_XS);
    const uint2*  par = (const uint2*)(sm + SM_PAR) + tap * TP;
    char* A = sm + SM_A;
    const int cabs = cq * 8;
    const int swc  = SWZ16(cq * 16, pb);   // p&7 == pb&7 (pi stride 32)

    #pragma unroll
    for (int pi = 0; pi < 4; pi++) {
        int p = pb + pi * 32;
        uint2 pr = par[p];
        int j0 = (int)(short)(pr.x & 0xFFFF);
        int j1 = (int)(short)(pr.x >> 16);
        __half2 f2 = __half2half2(__ushort_as_half((unsigned short)pr.y));
        uint4 u0, u1;
        if (__builtin_expect((unsigned)j0 < SPAN, 1)) {
            u0 = *(const uint4*)(xs + j0 * XSH + cabs);
        } else {
            int ja = min(max(j0 + base, 0), L_ - 1);
            __half2 h01 = __floats2half2_rn(xb[(size_t)cabs * L_ + ja],
                                            xb[(size_t)(cabs + 1) * L_ + ja]);
            __half2 h23 = __floats2half2_rn(xb[(size_t)(cabs + 2) * L_ + ja],
                                            xb[(size_t)(cabs + 3) * L_ + ja]);
            __half2 h45 = __floats2half2_rn(xb[(size_t)(cabs + 4) * L_ + ja],
                                            xb[(size_t)(cabs + 5) * L_ + ja]);
            __half2 h67 = __floats2half2_rn(xb[(size_t)(cabs + 6) * L_ + ja],
                                            xb[(size_t)(cabs + 7) * L_ + ja]);
            u0.x = *(uint32_t*)&h01; u0.y = *(uint32_t*)&h23;
            u0.z = *(uint32_t*)&h45; u0.w = *(uint32_t*)&h67;
        }
        if (__builtin_expect((unsigned)j1 < SPAN, 1)) {
            u1 = *(const uint4*)(xs + j1 * XSH + cabs);
        } else {
            int ja = min(max(j1 + base, 0), L_ - 1);
            __half2 h01 = __floats2half2_rn(xb[(size_t)cabs * L_ + ja],
                                            xb[(size_t)(cabs + 1) * L_ + ja]);
            __half2 h23 = __floats2half2_rn(xb[(size_t)(cabs + 2) * L_ + ja],
                                            xb[(size_t)(cabs + 3) * L_ + ja]);
            __half2 h45 = __floats2half2_rn(xb[(size_t)(cabs + 4) * L_ + ja],
                                            xb[(size_t)(cabs + 5) * L_ + ja]);
            __half2 h67 = __floats2half2_rn(xb[(size_t)(cabs + 6) * L_ + ja],
                                            xb[(size_t)(cabs + 7) * L_ + ja]);
            u1.x = *(uint32_t*)&h01; u1.y = *(uint32_t*)&h23;
            u1.z = *(uint32_t*)&h45; u1.w = *(uint32_t*)&h67;
        }
        __half2 g0, g1;
        uint4 st;
        g0 = *(__half2*)&u0.x; g1 = *(__half2*)&u1.x;
        { __half2 v = __hfma2(f2, __hsub2(g1, g0), g0); st.x = *(uint32_t*)&v; }
        g0 = *(__half2*)&u0.y; g1 = *(__half2*)&u1.y;
        { __half2 v = __hfma2(f2, __hsub2(g1, g0), g0); st.y = *(uint32_t*)&v; }
        g0 = *(__half2*)&u0.z; g1 = *(__half2*)&u1.z;
        { __half2 v = __hfma2(f2, __hsub2(g1, g0), g0); st.z = *(uint32_t*)&v; }
        g0 = *(__half2*)&u0.w; g1 = *(__half2*)&u1.w;
        { __half2 v = __hfma2(f2, __hsub2(g1, g0), g0); st.w = *(uint32_t*)&v; }
        *(uint4*)(A + p * 128 + swc) = st;
    }
}

// ---------------------------------------------------------------------------
__device__ __forceinline__ void load_wtap(char* sm, int tap, int t) {
    char* W = sm + SM_W;
    int o = t >> 2;
    int q = t & 3;
    #pragma unroll
    for (int h = 0; h < 2; h++) {
        int qq = q + h * 4;
        *(uint4*)(W + o * 128 + SWZ16(qq * 16, o)) =
            *(const uint4*)(g_w + (tap * 64 + o) * 64 + qq * 8);
    }
}

// ---------------------------------------------------------------------------
__global__ __launch_bounds__(NTHR, 4) void deform_main_kernel(
    const float* __restrict__ x,
    const float* __restrict__ off,
    const float* __restrict__ bias,
    float* __restrict__ out)
{
    extern __shared__ char sm[];

    const int b    = blockIdx.y;
    const int lo0  = blockIdx.x * TP;
    const int t    = threadIdx.x;
    const int lane = t & 31;
    const int wid  = t >> 5;
    const int base = lo0 - MARG;

    const float* xb = x + (size_t)b * CIN * L_;
    __half* xs = (__half*)(sm + SM_XS);
    uint2*  par = (uint2*)(sm + SM_PAR);

    // ---- x slice -> fp16 smem (float2 loads) ----
    {
        bool interior = (base >= 0) && (base + SPAN + 1 <= L_);
        for (int idx = t; idx < CIN * (SPAN / 2); idx += NTHR) {
            int c  = idx / (SPAN / 2);
            int qp = idx - c * (SPAN / 2);
            int q  = qp * 2;
            float2 v;
            if (interior) {
                v = *(const float2*)(xb + (size_t)c * L_ + base + q);
            } else {
                int ja0 = min(max(base + q, 0), L_ - 1);
                int ja1 = min(max(base + q + 1, 0), L_ - 1);
                v.x = xb[(size_t)c * L_ + ja0];
                v.y = xb[(size_t)c * L_ + ja1];
            }
            xs[q * XSH + c]       = __float2half_rn(v.x);
            xs[(q + 1) * XSH + c] = __float2half_rn(v.y);
        }
    }

    // ---- interp params (packed: j0|j1<<16, f as fp16) ----
    const float* offb = off + ((size_t)b * L_ + lo0) * KK;
    for (int idx = t; idx < TP * KK; idx += NTHR) {
        int p = idx / KK;
        int k = idx % KK;
        float T = (float)(lo0 + p + k) + offb[idx];
        T = fminf(fmaxf(T, 0.0f), (float)(LP - 1));
        int i0 = (int)floorf(T);
        i0 = min(max(i0, 0), LP - 2);
        float f = T - (float)i0;
        int j0 = i0 - PAD_;
        int j1 = i0 + 1 - PAD_;
        j0 = (j0 < 0) ? -j0 : j0;
        j1 = (j1 < 0) ? -j1 : j1;
        if (j0 >= L_) j0 = 2 * L_ - 2 - j0;
        if (j1 >= L_) j1 = 2 * L_ - 2 - j1;
        j0 -= base;
        j1 -= base;
        uint2 pr;
        pr.x = ((uint32_t)j0 & 0xFFFF) | (((uint32_t)j1 & 0xFFFF) << 16);
        pr.y = (uint32_t)__half_as_ushort(__float2half_rn(f));
        par[k * TP + p] = pr;
    }
    __syncthreads();

    // warp tiling: 4 (M) x 2 (N), warp tile 32x32
    const int m0 = (wid & 3) * 32;
    const int n0 = (wid >> 2) * 32;

    float acc[2][4][4];
    #pragma unroll
    for (int i = 0; i < 2; i++)
        #pragma unroll
        for (int j = 0; j < 4; j++)
            #pragma unroll
            for (int r = 0; r < 4; r++) acc[i][j][r] = 0.0f;

    for (int tap = 0; tap < KK; tap++) {
        load_wtap(sm, tap, t);
        build_tap(sm, xb, base, tap, t);
        __syncthreads();

        const char* A = sm + SM_A;
        const char* W = sm + SM_W;
        #pragma unroll
        for (int ks = 0; ks < 4; ks++) {
            uint32_t a[2][4], bb[4][2];
            int arow = lane & 15;
            int acb  = ks * 32 + (lane >> 4) * 16;
            #pragma unroll
            for (int mi = 0; mi < 2; mi++) {
                int row = m0 + mi * 16 + arow;
                ldm_x4(a[mi][0], a[mi][1], a[mi][2], a[mi][3],
                       A + row * 128 + SWZ16(acb, arow));
            }
            {
                int sub  = lane >> 3;
                int r    = lane & 7;
                int rowA = n0 + ((sub >> 1) << 3) + r;
                int colB = ks * 32 + (sub & 1) * 16;
                uint32_t r0, r1, r2, r3;
                ldm_x4(r0, r1, r2, r3, W + rowA * 128 + SWZ16(colB, r));
                bb[0][0] = r0; bb[0][1] = r1;
                bb[1][0] = r2; bb[1][1] = r3;
                ldm_x4(r0, r1, r2, r3, W + (rowA + 16) * 128 + SWZ16(colB, r));
                bb[2][0] = r0; bb[2][1] = r1;
                bb[3][0] = r2; bb[3][1] = r3;
            }
            #pragma unroll
            for (int mi = 0; mi < 2; mi++)
                #pragma unroll
                for (int ni = 0; ni < 4; ni++)
                    mma_fp16(acc[mi][ni], a[mi], bb[ni]);
        }
        if (tap < KK - 1) __syncthreads();
    }

    // ---- epilogue: direct stores (full 32B-sector utilization per STG) ----
    {
        const int g  = lane >> 2;
        const int tc = lane & 3;
        float* ob = out + (size_t)b * COUT * L_ + lo0;
        #pragma unroll
        for (int ni = 0; ni < 4; ni++) {
            int n = n0 + ni * 8 + tc * 2;
            float bs0 = __ldg(&bias[n]);
            float bs1 = __ldg(&bias[n + 1]);
            #pragma unroll
            for (int mi = 0; mi < 2; mi++) {
                int m = m0 + mi * 16 + g;
                ob[(size_t)n * L_ + m]           = acc[mi][ni][0] + bs0;
                ob[(size_t)(n + 1) * L_ + m]     = acc[mi][ni][1] + bs1;
                ob[(size_t)n * L_ + m + 8]       = acc[mi][ni][2] + bs0;
                ob[(size_t)(n + 1) * L_ + m + 8] = acc[mi][ni][3] + bs1;
            }
        }
    }
}

// ---------------------------------------------------------------------------
extern "C" void kernel_launch(void* const* d_in, const int* in_sizes, int n_in,
                              void* d_out, int out_size) {
    const float* x      = (const float*)d_in[0];
    const float* off    = (const float*)d_in[1];
    const float* weight = (const float*)d_in[2];
    const float* bias   = (const float*)d_in[3];
    float* out          = (float*)d_out;

    static bool attr_set = false;
    if (!attr_set) {
        cudaFuncSetAttribute(deform_main_kernel,
                             cudaFuncAttributeMaxDynamicSharedMemorySize, SM_TOTAL);
        attr_set = true;
    }

    wconv_kernel<<<KK * COUT, CIN>>>(weight);

    dim3 mg(L_ / TP, B_);
    deform_main_kernel<<<mg, NTHR, SM_TOTAL>>>(x, off, bias, out);
}

// round 12
// speedup vs baseline: 4.3904x; 1.0699x over previous
#include <cuda_runtime.h>
#include <cuda_fp16.h>
#include <cstdint>

// Problem constants
#define B_    8
#define CIN   64
#define COUT  64
#define L_    16384
#define KK    5
#define PAD_  2
#define LP    (L_ + 2*PAD_)
#define TP    128
#define NTHR  256

// x slice in smem (fp16, 128B rows, XOR-swizzled 16B units)
#define SPAN  142
#define MARG  6          // base = lo0 - MARG

// smem byte offsets
#define SM_XS    0                 // 142*128 = 18176 -> 18432
#define SM_A     18432             // 2 bufs * 128 rows * 128B = 32768
#define SM_PAR   51200             // 5*128*8 = 5120
#define SM_TOTAL 56320
#define A_STR    16384

// swizzle of 16B units within a 128B row
#define SWZ16(col, row) ((col) ^ (((row) & 7) * 16))

// W in mma-B fragment order: [tap][ngrp][ks][h][lane] -> uint4
__device__ uint4 g_wf[KK * 2 * 4 * 2 * 32];

// ---------------------------------------------------------------------------
// weight (o,c,k) -> fragment-ordered fp16
// ---------------------------------------------------------------------------
__global__ void wfrag_kernel(const float* __restrict__ w) {
    int idx = blockIdx.x * 256 + threadIdx.x;    // 2560 entries
    if (idx >= 2560) return;
    int lane = idx & 31;
    int h    = (idx >> 5) & 1;
    int ks   = (idx >> 6) & 3;
    int ngrp = (idx >> 8) & 1;
    int tap  = idx >> 9;
    int bn = lane >> 2;
    int q2 = (lane & 3) * 2;
    uint32_t r[4];
    #pragma unroll
    for (int j = 0; j < 2; j++) {
        int n = ngrp * 32 + (h * 2 + j) * 8 + bn;
        #pragma unroll
        for (int hf = 0; hf < 2; hf++) {
            int c0 = ks * 16 + hf * 8 + q2;
            __half2 p;
            p.x = __float2half_rn(w[n * (CIN * KK) + c0 * KK + tap]);
            p.y = __float2half_rn(w[n * (CIN * KK) + (c0 + 1) * KK + tap]);
            r[j * 2 + hf] = *(uint32_t*)&p;
        }
    }
    g_wf[idx] = make_uint4(r[0], r[1], r[2], r[3]);
}

// ---------------------------------------------------------------------------
__device__ __forceinline__ void ldm_x4(uint32_t& r0, uint32_t& r1, uint32_t& r2, uint32_t& r3,
                                       const void* p) {
    uint32_t a = (uint32_t)__cvta_generic_to_shared(p);
    asm volatile("ldmatrix.sync.aligned.m8n8.x4.shared.b16 {%0,%1,%2,%3}, [%4];"
                 : "=r"(r0), "=r"(r1), "=r"(r2), "=r"(r3) : "r"(a));
}

__device__ __forceinline__ void mma_fp16(float* c, const uint32_t* a,
                                         uint32_t b0, uint32_t b1) {
    asm volatile(
        "mma.sync.aligned.m16n8k16.row.col.f32.f16.f16.f32 "
        "{%0,%1,%2,%3}, {%4,%5,%6,%7}, {%8,%9}, {%0,%1,%2,%3};"
        : "+f"(c[0]), "+f"(c[1]), "+f"(c[2]), "+f"(c[3])
        : "r"(a[0]), "r"(a[1]), "r"(a[2]), "r"(a[3]), "r"(b0), "r"(b1));
}

// ---------------------------------------------------------------------------
// build full-tap A tile (128 pos x 64 ch). 8 channels/thread, LDS.128 gathers
// from the swizzled 128B-row x slice.
// ---------------------------------------------------------------------------
__device__ __forceinline__ void build_tap(char* sm, const float* __restrict__ xb,
                                          int base, int tap, int buf, int t) {
    const int cq = t & 7;           // 8 channels: 8*cq .. 8*cq+7
    const int pb = t >> 3;          // 32 position groups
    const uint2* par = (const uint2*)(sm + SM_PAR) + tap * TP;
    char* A = sm + SM_A + buf * A_STR;
    const int cabs = cq * 8;
    const int swc  = SWZ16(cq * 16, pb);   // p&7 == pb&7 (pi stride 32)

    #pragma unroll
    for (int pi = 0; pi < 4; pi++) {
        int p = pb + pi * 32;
        uint2 pr = par[p];
        int j0 = (int)(short)(pr.x & 0xFFFF);
        int j1 = (int)(short)(pr.x >> 16);
        __half2 f2 = __half2half2(__ushort_as_half((unsigned short)pr.y));
        uint4 u0, u1;
        if (__builtin_expect((unsigned)j0 < SPAN, 1)) {
            u0 = *(const uint4*)(sm + SM_XS + j0 * 128 + SWZ16(cq * 16, j0));
        } else {
            int ja = min(max(j0 + base, 0), L_ - 1);
            __half2 h01 = __floats2half2_rn(xb[(size_t)cabs * L_ + ja],
                                            xb[(size_t)(cabs + 1) * L_ + ja]);
            __half2 h23 = __floats2half2_rn(xb[(size_t)(cabs + 2) * L_ + ja],
                                            xb[(size_t)(cabs + 3) * L_ + ja]);
            __half2 h45 = __floats2half2_rn(xb[(size_t)(cabs + 4) * L_ + ja],
                                            xb[(size_t)(cabs + 5) * L_ + ja]);
            __half2 h67 = __floats2half2_rn(xb[(size_t)(cabs + 6) * L_ + ja],
                                            xb[(size_t)(cabs + 7) * L_ + ja]);
            u0.x = *(uint32_t*)&h01; u0.y = *(uint32_t*)&h23;
            u0.z = *(uint32_t*)&h45; u0.w = *(uint32_t*)&h67;
        }
        if (__builtin_expect((unsigned)j1 < SPAN, 1)) {
            u1 = *(const uint4*)(sm + SM_XS + j1 * 128 + SWZ16(cq * 16, j1));
        } else {
            int ja = min(max(j1 + base, 0), L_ - 1);
            __half2 h01 = __floats2half2_rn(xb[(size_t)cabs * L_ + ja],
                                            xb[(size_t)(cabs + 1) * L_ + ja]);
            __half2 h23 = __floats2half2_rn(xb[(size_t)(cabs + 2) * L_ + ja],
                                            xb[(size_t)(cabs + 3) * L_ + ja]);
            __half2 h45 = __floats2half2_rn(xb[(size_t)(cabs + 4) * L_ + ja],
                                            xb[(size_t)(cabs + 5) * L_ + ja]);
            __half2 h67 = __floats2half2_rn(xb[(size_t)(cabs + 6) * L_ + ja],
                                            xb[(size_t)(cabs + 7) * L_ + ja]);
            u1.x = *(uint32_t*)&h01; u1.y = *(uint32_t*)&h23;
            u1.z = *(uint32_t*)&h45; u1.w = *(uint32_t*)&h67;
        }
        __half2 g0, g1;
        uint4 st;
        g0 = *(__half2*)&u0.x; g1 = *(__half2*)&u1.x;
        { __half2 v = __hfma2(f2, __hsub2(g1, g0), g0); st.x = *(uint32_t*)&v; }
        g0 = *(__half2*)&u0.y; g1 = *(__half2*)&u1.y;
        { __half2 v = __hfma2(f2, __hsub2(g1, g0), g0); st.y = *(uint32_t*)&v; }
        g0 = *(__half2*)&u0.z; g1 = *(__half2*)&u1.z;
        { __half2 v = __hfma2(f2, __hsub2(g1, g0), g0); st.z = *(uint32_t*)&v; }
        g0 = *(__half2*)&u0.w; g1 = *(__half2*)&u1.w;
        { __half2 v = __hfma2(f2, __hsub2(g1, g0), g0); st.w = *(uint32_t*)&v; }
        *(uint4*)(A + p * 128 + swc) = st;
    }
}

// ---------------------------------------------------------------------------
__global__ __launch_bounds__(NTHR, 4) void deform_main_kernel(
    const float* __restrict__ x,
    const float* __restrict__ off,
    const float* __restrict__ bias,
    float* __restrict__ out)
{
    extern __shared__ char sm[];

    const int b    = blockIdx.y;
    const int lo0  = blockIdx.x * TP;
    const int t    = threadIdx.x;
    const int lane = t & 31;
    const int wid  = t >> 5;
    const int base = lo0 - MARG;

    const float* xb = x + (size_t)b * CIN * L_;
    uint2* par = (uint2*)(sm + SM_PAR);

    // ---- x slice -> fp16 swizzled smem ----
    // thread layout: per warp, one channel-pair row; lanes sweep q (coalesced LDG,
    // 4-way-max STS via XOR swizzle).
    {
        bool interior = (base >= 0) && (base + SPAN <= L_);
        for (int i = wid; i < 32; i += 8) {           // channel pair i: ch 2i, 2i+1
            const float* r0 = xb + (size_t)(2 * i) * L_;
            const float* r1 = r0 + L_;
            for (int q = lane; q < SPAN; q += 32) {
                float v0, v1;
                if (interior) {
                    v0 = r0[base + q];
                    v1 = r1[base + q];
                } else {
                    int ja = min(max(base + q, 0), L_ - 1);
                    v0 = r0[ja];
                    v1 = r1[ja];
                }
                __half2 h = __floats2half2_rn(v0, v1);
                *(__half2*)(sm + SM_XS + q * 128 +
                            ((((i >> 2) ^ (q & 7)) << 4) | ((i & 3) << 2))) = h;
            }
        }
    }

    // ---- interp params (packed: j0|j1<<16, f as fp16) ----
    const float* offb = off + ((size_t)b * L_ + lo0) * KK;
    for (int idx = t; idx < TP * KK; idx += NTHR) {
        int p = idx / KK;
        int k = idx % KK;
        float T = (float)(lo0 + p + k) + offb[idx];
        T = fminf(fmaxf(T, 0.0f), (float)(LP - 1));
        int i0 = (int)floorf(T);
        i0 = min(max(i0, 0), LP - 2);
        float f = T - (float)i0;
        int j0 = i0 - PAD_;
        int j1 = i0 + 1 - PAD_;
        j0 = (j0 < 0) ? -j0 : j0;
        j1 = (j1 < 0) ? -j1 : j1;
        if (j0 >= L_) j0 = 2 * L_ - 2 - j0;
        if (j1 >= L_) j1 = 2 * L_ - 2 - j1;
        j0 -= base;
        j1 -= base;
        uint2 pr;
        pr.x = ((uint32_t)j0 & 0xFFFF) | (((uint32_t)j1 & 0xFFFF) << 16);
        pr.y = (uint32_t)__half_as_ushort(__float2half_rn(f));
        par[k * TP + p] = pr;
    }
    __syncthreads();

    build_tap(sm, xb, base, 0, 0, t);
    __syncthreads();

    // warp tiling: 4 (M) x 2 (N), warp tile 32x32
    const int m0 = (wid & 3) * 32;
    const int n0 = (wid >> 2) * 32;

    float acc[2][4][4];
    #pragma unroll
    for (int i = 0; i < 2; i++)
        #pragma unroll
        for (int j = 0; j < 4; j++)
            #pragma unroll
            for (int r = 0; r < 4; r++) acc[i][j][r] = 0.0f;

    for (int tap = 0; tap < KK; tap++) {
        if (tap < KK - 1)
            build_tap(sm, xb, base, tap + 1, (tap + 1) & 1, t);

        const char* A = sm + SM_A + (tap & 1) * A_STR;
        const uint4* wfb = g_wf + (size_t)(tap * 2 + (n0 >> 5)) * 8 * 32;
        #pragma unroll
        for (int ks = 0; ks < 4; ks++) {
            uint32_t a[2][4];
            int arow = lane & 15;
            int acb  = ks * 32 + (lane >> 4) * 16;
            #pragma unroll
            for (int mi = 0; mi < 2; mi++) {
                int row = m0 + mi * 16 + arow;
                ldm_x4(a[mi][0], a[mi][1], a[mi][2], a[mi][3],
                       A + row * 128 + SWZ16(acb, arow));
            }
            uint4 Ua = __ldg(wfb + (ks * 2 + 0) * 32 + lane);   // ni 0,1
            uint4 Ub = __ldg(wfb + (ks * 2 + 1) * 32 + lane);   // ni 2,3
            #pragma unroll
            for (int mi = 0; mi < 2; mi++) {
                mma_fp16(acc[mi][0], a[mi], Ua.x, Ua.y);
                mma_fp16(acc[mi][1], a[mi], Ua.z, Ua.w);
                mma_fp16(acc[mi][2], a[mi], Ub.x, Ub.y);
                mma_fp16(acc[mi][3], a[mi], Ub.z, Ub.w);
            }
        }
        __syncthreads();
    }

    // ---- epilogue: direct stores (full 32B-sector utilization per STG) ----
    {
        const int g  = lane >> 2;
        const int tc = lane & 3;
        float* ob = out + (size_t)b * COUT * L_ + lo0;
        #pragma unroll
        for (int ni = 0; ni < 4; ni++) {
            int n = n0 + ni * 8 + tc * 2;
            float bs0 = __ldg(&bias[n]);
            float bs1 = __ldg(&bias[n + 1]);
            #pragma unroll
            for (int mi = 0; mi < 2; mi++) {
                int m = m0 + mi * 16 + g;
                ob[(size_t)n * L_ + m]           = acc[mi][ni][0] + bs0;
                ob[(size_t)(n + 1) * L_ + m]     = acc[mi][ni][1] + bs1;
                ob[(size_t)n * L_ + m + 8]       = acc[mi][ni][2] + bs0;
                ob[(size_t)(n + 1) * L_ + m + 8] = acc[mi][ni][3] + bs1;
            }
        }
    }
}

// ---------------------------------------------------------------------------
extern "C" void kernel_launch(void* const* d_in, const int* in_sizes, int n_in,
                              void* d_out, int out_size) {
    const float* x      = (const float*)d_in[0];
    const float* off    = (const float*)d_in[1];
    const float* weight = (const float*)d_in[2];
    const float* bias   = (const float*)d_in[3];
    float* out          = (float*)d_out;

    static bool attr_set = false;
    if (!attr_set) {
        cudaFuncSetAttribute(deform_main_kernel,
                             cudaFuncAttributeMaxDynamicSharedMemorySize, SM_TOTAL);
        attr_set = true;
    }

    wfrag_kernel<<<10, 256>>>(weight);

    dim3 mg(L_ / TP, B_);
    deform_main_kernel<<<mg, NTHR, SM_TOTAL>>>(x, off, bias, out);
}